// round 5
// baseline (speedup 1.0000x reference)
#include <cuda_runtime.h>
#include <math.h>

#define NLAY 4
#define NBAT 16384
#define NR   256

// ---------------- scratch: device globals (no runtime allocation allowed) ----------------
__device__ float g_ugacc[NBAT * 16];                 // [b][l*4+j]  h_stacked @ w_ug part (layer-independent)
__device__ float g_gvals[NBAT * 4];                  // [b][g]      tanh global gates for current layer
__device__ float g_gacc[(size_t)NBAT * NR];          // [b][q]      sum_g g * (h_g @ Wuij^T) (+bias term)
__device__ float g_zr[(size_t)NBAT * 2 * NR];        // [b][0:256]=z pre-act, [256:512]=r pre-act
__device__ float g_cand[(size_t)NBAT * NR];          // [b][q]      x @ w_j1j^T + b

// ---------------- packed fp32x2 (Blackwell FFMA2 — PTX-only instruction) ----------------
__device__ __forceinline__ unsigned long long f2_fma(unsigned long long a, unsigned long long b,
                                                     unsigned long long c) {
    unsigned long long d;
    asm("fma.rn.f32x2 %0, %1, %2, %3;" : "=l"(d) : "l"(a), "l"(b), "l"(c));
    return d;
}
__device__ __forceinline__ unsigned long long f2_dup(float x) {
    unsigned long long d;
    unsigned int u = __float_as_uint(x);
    asm("mov.b64 %0, {%1, %1};" : "=l"(d) : "r"(u));
    return d;
}
__device__ __forceinline__ void f2_unpack(unsigned long long v, float& lo, float& hi) {
    unsigned int l_, h_;
    asm("mov.b64 {%0, %1}, %2;" : "=r"(l_), "=r"(h_) : "l"(v));
    lo = __uint_as_float(l_);
    hi = __uint_as_float(h_);
}

// ---------------- shared 8x(128x128) micro-kernel: acc2[ip][j] packs output rows (2ip, 2ip+1) ----------------
__device__ __forceinline__ void mm_kk8(const float (*As)[128], const float (*Bs)[128],
                                       unsigned long long acc2[4][8], int tm8, int tn8) {
#pragma unroll
    for (int kk = 0; kk < 8; ++kk) {
        ulonglong2 av0 = *(const ulonglong2*)&As[kk][tm8];
        ulonglong2 av1 = *(const ulonglong2*)&As[kk][tm8 + 4];
        unsigned long long a2[4] = {av0.x, av0.y, av1.x, av1.y};
        float4 b0 = *(const float4*)&Bs[kk][tn8];
        float4 b1 = *(const float4*)&Bs[kk][tn8 + 4];
        unsigned long long b2[8] = {f2_dup(b0.x), f2_dup(b0.y), f2_dup(b0.z), f2_dup(b0.w),
                                    f2_dup(b1.x), f2_dup(b1.y), f2_dup(b1.z), f2_dup(b1.w)};
#pragma unroll
        for (int ip = 0; ip < 4; ++ip)
#pragma unroll
            for (int j = 0; j < 8; ++j)
                acc2[ip][j] = f2_fma(a2[ip], b2[j], acc2[ip][j]);
    }
}

// ---------------- generic C[M,N] = A0@W0^T (+ A1@W1^T) + biases  (W: [N,256] row-major) ----------------
__device__ __forceinline__ void sgemm_body(const float* __restrict__ A0, const float* __restrict__ W0,
                                           const float* __restrict__ A1, const float* __restrict__ W1,
                                           const float* __restrict__ b0, const float* __restrict__ b1,
                                           float* __restrict__ C, int N) {
    __shared__ __align__(16) float As[8][128];
    __shared__ __align__(16) float Bs[8][128];
    const int tid = threadIdx.x;
    const int bm = blockIdx.x * 128, bn = blockIdx.y * 128;
    const int tm8 = (tid >> 4) * 8, tn8 = (tid & 15) * 8;
    const int lm = tid >> 1, lk = (tid & 1) * 4;

    unsigned long long acc2[4][8];
#pragma unroll
    for (int i = 0; i < 4; ++i)
#pragma unroll
        for (int j = 0; j < 8; ++j) acc2[i][j] = 0ULL;

    for (int pass = 0; pass < 2; ++pass) {
        const float* A = (pass == 0) ? A0 : A1;
        const float* W = (pass == 0) ? W0 : W1;
        if (A == nullptr) break;
        const float* Ar = A + (size_t)(bm + lm) * 256 + lk;
        const float* Wr = W + (size_t)(bn + lm) * 256 + lk;
#pragma unroll 4
        for (int k0 = 0; k0 < 256; k0 += 8) {
            float4 av = *(const float4*)(Ar + k0);
            float4 wv = *(const float4*)(Wr + k0);
            __syncthreads();
            As[lk + 0][lm] = av.x; As[lk + 1][lm] = av.y;
            As[lk + 2][lm] = av.z; As[lk + 3][lm] = av.w;
            Bs[lk + 0][lm] = wv.x; Bs[lk + 1][lm] = wv.y;
            Bs[lk + 2][lm] = wv.z; Bs[lk + 3][lm] = wv.w;
            __syncthreads();
            mm_kk8(As, Bs, acc2, tm8, tn8);
        }
    }

    float bv[8];
#pragma unroll
    for (int j = 0; j < 8; ++j) {
        int n = bn + tn8 + j;
        float v = b0 ? b0[n] : 0.f;
        if (b1) v += b1[n];
        bv[j] = v;
    }
#pragma unroll
    for (int ip = 0; ip < 4; ++ip) {
        float r0[8], r1[8];
#pragma unroll
        for (int j = 0; j < 8; ++j) {
            f2_unpack(acc2[ip][j], r0[j], r1[j]);
            r0[j] += bv[j];
            r1[j] += bv[j];
        }
        int m0 = bm + tm8 + 2 * ip;
        float4 o;
        o.x = r0[0]; o.y = r0[1]; o.z = r0[2]; o.w = r0[3];
        *(float4*)(C + (size_t)m0 * N + bn + tn8) = o;
        o.x = r0[4]; o.y = r0[5]; o.z = r0[6]; o.w = r0[7];
        *(float4*)(C + (size_t)m0 * N + bn + tn8 + 4) = o;
        o.x = r1[0]; o.y = r1[1]; o.z = r1[2]; o.w = r1[3];
        *(float4*)(C + (size_t)(m0 + 1) * N + bn + tn8) = o;
        o.x = r1[4]; o.y = r1[5]; o.z = r1[6]; o.w = r1[7];
        *(float4*)(C + (size_t)(m0 + 1) * N + bn + tn8 + 4) = o;
    }
}

__global__ void __launch_bounds__(256, 2)
zr_gemm_k(const float* __restrict__ A0, const float* __restrict__ W0,
          const float* __restrict__ A1, const float* __restrict__ W1,
          const float* __restrict__ b0, const float* __restrict__ b1) {
    sgemm_body(A0, W0, A1, W1, b0, b1, g_zr, 512);
}

__global__ void __launch_bounds__(256, 2)
cand_gemm_k(const float* __restrict__ A0, const float* __restrict__ W0, const float* __restrict__ b0) {
    sgemm_body(A0, W0, nullptr, nullptr, b0, nullptr, g_cand, 256);
}

// ---------------- g_acc GEMM: K'=1024 over (g,k); A'[b,g*256+k] = gvals[b,g]*prev[g,b,k] ----------------
__global__ void __launch_bounds__(256, 2)
gacc_gemm_k(const float* __restrict__ prev, const float* __restrict__ wuij,
            const float* __restrict__ buij) {
    __shared__ __align__(16) float As[8][128];
    __shared__ __align__(16) float Bs[8][128];
    const int tid = threadIdx.x;
    const int bm = blockIdx.x * 128, bn = blockIdx.y * 128;
    const int tm8 = (tid >> 4) * 8, tn8 = (tid & 15) * 8;
    const int lm = tid >> 1, lk = (tid & 1) * 4;
    const int arow = bm + lm;

    unsigned long long acc2[4][8];
#pragma unroll
    for (int i = 0; i < 4; ++i)
#pragma unroll
        for (int j = 0; j < 8; ++j) acc2[i][j] = 0ULL;

#pragma unroll 2
    for (int k0 = 0; k0 < 1024; k0 += 8) {
        const int g = k0 >> 8, kl = k0 & 255;
        float sc = g_gvals[arow * 4 + g];
        float4 av = *(const float4*)(prev + ((size_t)g * NBAT + arow) * 256 + kl + lk);
        float4 wv = *(const float4*)(wuij + ((size_t)g * 256 + bn + lm) * 256 + kl + lk);
        av.x *= sc; av.y *= sc; av.z *= sc; av.w *= sc;
        __syncthreads();
        As[lk + 0][lm] = av.x; As[lk + 1][lm] = av.y;
        As[lk + 2][lm] = av.z; As[lk + 3][lm] = av.w;
        Bs[lk + 0][lm] = wv.x; Bs[lk + 1][lm] = wv.y;
        Bs[lk + 2][lm] = wv.z; Bs[lk + 3][lm] = wv.w;
        __syncthreads();
        mm_kk8(As, Bs, acc2, tm8, tn8);
    }

    // epilogue: += sum_g gvals[b,g] * b_uij[l,g,q]
#pragma unroll
    for (int ip = 0; ip < 4; ++ip) {
        float r0[8], r1[8];
#pragma unroll
        for (int j = 0; j < 8; ++j) f2_unpack(acc2[ip][j], r0[j], r1[j]);
        int m0 = bm + tm8 + 2 * ip;
        float ga0 = g_gvals[m0 * 4 + 0], ga1 = g_gvals[m0 * 4 + 1];
        float ga2 = g_gvals[m0 * 4 + 2], ga3 = g_gvals[m0 * 4 + 3];
        float gb0 = g_gvals[(m0 + 1) * 4 + 0], gb1 = g_gvals[(m0 + 1) * 4 + 1];
        float gb2 = g_gvals[(m0 + 1) * 4 + 2], gb3 = g_gvals[(m0 + 1) * 4 + 3];
#pragma unroll
        for (int j = 0; j < 8; ++j) {
            int q = bn + tn8 + j;
            float bq0 = buij[q], bq1 = buij[256 + q], bq2 = buij[512 + q], bq3 = buij[768 + q];
            r0[j] += ga0 * bq0 + ga1 * bq1 + ga2 * bq2 + ga3 * bq3;
            r1[j] += gb0 * bq0 + gb1 * bq1 + gb2 * bq2 + gb3 * bq3;
        }
        float4 o;
        o.x = r0[0]; o.y = r0[1]; o.z = r0[2]; o.w = r0[3];
        *(float4*)(g_gacc + (size_t)m0 * 256 + bn + tn8) = o;
        o.x = r0[4]; o.y = r0[5]; o.z = r0[6]; o.w = r0[7];
        *(float4*)(g_gacc + (size_t)m0 * 256 + bn + tn8 + 4) = o;
        o.x = r1[0]; o.y = r1[1]; o.z = r1[2]; o.w = r1[3];
        *(float4*)(g_gacc + (size_t)(m0 + 1) * 256 + bn + tn8) = o;
        o.x = r1[4]; o.y = r1[5]; o.z = r1[6]; o.w = r1[7];
        *(float4*)(g_gacc + (size_t)(m0 + 1) * 256 + bn + tn8 + 4) = o;
    }
}

// ---------------- h_stacked @ w_ug[l].T for ALL (l,j) at once (prev_hs-only, hoisted out of layer loop) ----------------
// grid (NBAT/8, 2): blockIdx.y selects 8 of the 16 (l,j) pairs; one warp per batch row.
__global__ void ug_precompute_k(const float* __restrict__ prev, const float* __restrict__ wug) {
    __shared__ float ws[8 * 1024];  // 32 KB
    const int ljbase = blockIdx.y * 8;
    {
        const float4* src = (const float4*)(wug + (size_t)ljbase * 1024);
        float4* dst = (float4*)ws;
#pragma unroll
        for (int i = 0; i < 8; ++i) dst[threadIdx.x + i * 256] = src[threadIdx.x + i * 256];
    }
    __syncthreads();
    const int warp = threadIdx.x >> 5, lane = threadIdx.x & 31;
    const int b = blockIdx.x * 8 + warp;
    float acc[8];
#pragma unroll
    for (int t = 0; t < 8; ++t) acc[t] = 0.f;
#pragma unroll
    for (int g = 0; g < 4; ++g) {
        const float* hrow = prev + ((size_t)g * NBAT + b) * 256;
#pragma unroll
        for (int rr = 0; rr < 8; ++rr) {
            int r = rr * 32 + lane;
            float h = hrow[r];
#pragma unroll
            for (int t = 0; t < 8; ++t) acc[t] += h * ws[t * 1024 + g * 256 + r];
        }
    }
#pragma unroll
    for (int t = 0; t < 8; ++t) {
        float v = acc[t];
#pragma unroll
        for (int o = 16; o > 0; o >>= 1) v += __shfl_xor_sync(0xffffffffu, v, o);
        if (lane == 0) g_ugacc[(size_t)b * 16 + ljbase + t] = v;
    }
}

// ---------------- per-layer global gates: g[b,j] = tanh(x_l . w_g[l,j] + ugacc + biases) ----------------
__global__ void xg_k(const float* __restrict__ xl, const float* __restrict__ wg,
                     const float* __restrict__ bg, const float* __restrict__ bug, int l) {
    __shared__ float ws[1024];
#pragma unroll
    for (int i = 0; i < 4; ++i) ws[threadIdx.x + i * 256] = wg[threadIdx.x + i * 256];
    __syncthreads();
    const int warp = threadIdx.x >> 5, lane = threadIdx.x & 31;
    const int b = blockIdx.x * 8 + warp;
    const float* xrow = xl + (size_t)b * 256;
    float acc[4] = {0.f, 0.f, 0.f, 0.f};
#pragma unroll
    for (int rr = 0; rr < 8; ++rr) {
        int r = rr * 32 + lane;
        float xv = xrow[r];
#pragma unroll
        for (int j = 0; j < 4; ++j) acc[j] += xv * ws[j * 256 + r];
    }
#pragma unroll
    for (int j = 0; j < 4; ++j) {
        float v = acc[j];
#pragma unroll
        for (int o = 16; o > 0; o >>= 1) v += __shfl_xor_sync(0xffffffffu, v, o);
        if (lane == 0)
            g_gvals[b * 4 + j] = tanhf(v + g_ugacc[(size_t)b * 16 + l * 4 + j] + bg[j] + bug[j]);
    }
}

// ---------------- final GRU pointwise ----------------
__global__ void pointwise_k(const float* __restrict__ hprev, float* __restrict__ out) {
    size_t idx = (size_t)blockIdx.x * 256 + threadIdx.x;
    int b = (int)(idx >> 8);
    int r = (int)(idx & 255);
    float zpre = g_zr[(size_t)b * 512 + r];
    float rpre = g_zr[(size_t)b * 512 + 256 + r];
    float z = 1.f / (1.f + expf(-zpre));
    float rt = 1.f / (1.f + expf(-rpre));
    float hc = tanhf(g_cand[idx] + rt * g_gacc[idx]);
    float hp = hprev[idx];
    out[idx] = (1.f - z) * hp + z * hc;
}

// ---------------- launch ----------------
extern "C" void kernel_launch(void* const* d_in, const int* in_sizes, int n_in,
                              void* d_out, int out_size) {
    (void)in_sizes; (void)n_in; (void)out_size;
    const float* x     = (const float*)d_in[0];
    const float* prev  = (const float*)d_in[1];
    const float* w_i2h = (const float*)d_in[2];
    const float* b_i2h = (const float*)d_in[3];
    const float* w_h2h = (const float*)d_in[4];
    const float* b_h2h = (const float*)d_in[5];
    const float* w_j1j = (const float*)d_in[6];
    const float* b_j1j = (const float*)d_in[7];
    const float* w_g   = (const float*)d_in[8];
    const float* b_g   = (const float*)d_in[9];
    const float* w_ug  = (const float*)d_in[10];
    const float* b_ug  = (const float*)d_in[11];
    const float* w_uij = (const float*)d_in[12];
    const float* b_uij = (const float*)d_in[13];
    float* out = (float*)d_out;

    // layer-independent: h_stacked @ w_ug[l].T for all (l, j)
    ug_precompute_k<<<dim3(NBAT / 8, 2), 256>>>(prev, w_ug);

    for (int l = 0; l < NLAY; ++l) {
        const float* xl = (l == 0) ? x : out + (size_t)(l - 1) * NBAT * NR;

        // global gates for this layer (needs x_l)
        xg_k<<<NBAT / 8, 256>>>(xl, w_g + (size_t)l * 4 * 256, b_g + l * 4, b_ug + l * 4, l);

        // g_acc = sum_g g[b,g] * (h_g @ Wuij[l,g]^T + b_uij[l,g])   [fused, no uij materialization]
        gacc_gemm_k<<<dim3(NBAT / 128, 2), 256>>>(prev, w_uij + (size_t)l * 4 * 256 * 256,
                                                  b_uij + (size_t)l * 4 * 256);

        // z/r pre-activations: x@w_i2h^T + h_l@w_h2h^T + biases   [B,512]
        zr_gemm_k<<<dim3(NBAT / 128, 4), 256>>>(xl, w_i2h + (size_t)l * 512 * 256,
                                                prev + (size_t)l * NBAT * 256,
                                                w_h2h + (size_t)l * 512 * 256,
                                                b_i2h + (size_t)l * 512, b_h2h + (size_t)l * 512);

        // candidate linear part: x@w_j1j^T + b   [B,256]
        cand_gemm_k<<<dim3(NBAT / 128, 2), 256>>>(xl, w_j1j + (size_t)l * 256 * 256,
                                                  b_j1j + (size_t)l * 256);

        // ht = (1-z)*h_prev + z*tanh(cand + r*g_acc)
        pointwise_k<<<(NBAT * NR) / 256, 256>>>(prev + (size_t)l * NBAT * 256,
                                                out + (size_t)l * NBAT * 256);
    }
}

// round 7
// speedup vs baseline: 2.1962x; 2.1962x over previous
#include <cuda_runtime.h>
#include <cuda_bf16.h>
#include <math.h>
#include <stdint.h>

#define NLAY 4
#define NBAT 16384
#define NR   256

// ======================= device scratch (no runtime alloc) =======================
// Activations, row-major bf16 hi/lo
__device__ __align__(16) __nv_bfloat16 d_xh[(size_t)NBAT * 256], d_xl[(size_t)NBAT * 256];
__device__ __align__(16) __nv_bfloat16 d_ph[(size_t)NLAY * NBAT * 256], d_pl[(size_t)NLAY * NBAT * 256];
__device__ __align__(16) __nv_bfloat16 d_ash[(size_t)NBAT * 1024], d_asl[(size_t)NBAT * 1024];
// Weights transposed to [K=256][N] bf16 hi/lo
__device__ __align__(16) __nv_bfloat16 d_wih[(size_t)NLAY * 256 * 512], d_wil[(size_t)NLAY * 256 * 512];
__device__ __align__(16) __nv_bfloat16 d_whh[(size_t)NLAY * 256 * 512], d_whl[(size_t)NLAY * 256 * 512];
__device__ __align__(16) __nv_bfloat16 d_wjh[(size_t)NLAY * 256 * 256], d_wjl[(size_t)NLAY * 256 * 256];
__device__ __align__(16) __nv_bfloat16 d_wuh[(size_t)NLAY * 4 * 256 * 256], d_wul[(size_t)NLAY * 4 * 256 * 256];
// fp32 intermediates
__device__ float g_ugacc[NBAT * 16];
__device__ float g_gvals[NBAT * 4];
__device__ float g_zr[(size_t)NBAT * 2 * NR];
__device__ float g_cand[(size_t)NBAT * NR];
__device__ float g_gacc[(size_t)NBAT * NR];

// ======================= PTX helpers (base sm_100 features only) =======================
__device__ __forceinline__ uint32_t s2u(const void* p) {
    uint32_t a;
    asm("{ .reg .u64 t; cvta.to.shared.u64 t, %1; cvt.u32.u64 %0, t; }" : "=r"(a) : "l"(p));
    return a;
}
__device__ __forceinline__ void cp16(uint32_t dst, const void* src) {
    asm volatile("cp.async.cg.shared.global [%0], [%1], 16;" ::"r"(dst), "l"(src) : "memory");
}
__device__ __forceinline__ void cp_commit() { asm volatile("cp.async.commit_group;" ::: "memory"); }
template <int N>
__device__ __forceinline__ void cp_wait() { asm volatile("cp.async.wait_group %0;" ::"n"(N) : "memory"); }
__device__ __forceinline__ void ldsm4(uint32_t* r, uint32_t a) {
    asm volatile("ldmatrix.sync.aligned.m8n8.x4.shared.b16 {%0,%1,%2,%3}, [%4];"
                 : "=r"(r[0]), "=r"(r[1]), "=r"(r[2]), "=r"(r[3]) : "r"(a));
}
__device__ __forceinline__ void ldsm4t(uint32_t* r, uint32_t a) {
    asm volatile("ldmatrix.sync.aligned.m8n8.x4.trans.shared.b16 {%0,%1,%2,%3}, [%4];"
                 : "=r"(r[0]), "=r"(r[1]), "=r"(r[2]), "=r"(r[3]) : "r"(a));
}
__device__ __forceinline__ void mma16816(float* c, const uint32_t* a, const uint32_t* b) {
    asm volatile(
        "mma.sync.aligned.m16n8k16.row.col.f32.bf16.bf16.f32 "
        "{%0,%1,%2,%3}, {%4,%5,%6,%7}, {%8,%9}, {%0,%1,%2,%3};"
        : "+f"(c[0]), "+f"(c[1]), "+f"(c[2]), "+f"(c[3])
        : "r"(a[0]), "r"(a[1]), "r"(a[2]), "r"(a[3]), "r"(b[0]), "r"(b[1]));
}
__device__ __forceinline__ void bsplit(float v, __nv_bfloat16& h, __nv_bfloat16& l) {
    h = __float2bfloat16(v);
    l = __float2bfloat16(v - __bfloat162float(h));
}

// ======================= prep kernels =======================
// row-major fp32 -> hi/lo bf16 (layout-preserving), 4 elems/thread
__global__ void split_k(const float* __restrict__ src, __nv_bfloat16* __restrict__ hi,
                        __nv_bfloat16* __restrict__ lo) {
    size_t i = (size_t)blockIdx.x * 256 + threadIdx.x;
    float4 v = ((const float4*)src)[i];
    __nv_bfloat16 h0, h1, h2, h3, l0, l1, l2, l3;
    bsplit(v.x, h0, l0); bsplit(v.y, h1, l1); bsplit(v.z, h2, l2); bsplit(v.w, h3, l3);
    ((__nv_bfloat162*)hi)[2 * i]     = __nv_bfloat162(h0, h1);
    ((__nv_bfloat162*)hi)[2 * i + 1] = __nv_bfloat162(h2, h3);
    ((__nv_bfloat162*)lo)[2 * i]     = __nv_bfloat162(l0, l1);
    ((__nv_bfloat162*)lo)[2 * i + 1] = __nv_bfloat162(l2, l3);
}
// W [batch][rows][256] fp32 -> Wt [batch][256][rows] bf16 hi/lo (transpose + split)
__global__ void prep_w_k(const float* __restrict__ src, __nv_bfloat16* __restrict__ hi,
                         __nv_bfloat16* __restrict__ lo, int rows) {
    __shared__ float t[32][33];
    const float* s = src + (size_t)blockIdx.z * rows * 256;
    __nv_bfloat16* ho = hi + (size_t)blockIdx.z * rows * 256;
    __nv_bfloat16* lw = lo + (size_t)blockIdx.z * rows * 256;
    int r0 = blockIdx.x * 32, c0 = blockIdx.y * 32;
#pragma unroll
    for (int i = threadIdx.y; i < 32; i += 8)
        t[i][threadIdx.x] = s[(size_t)(r0 + i) * 256 + c0 + threadIdx.x];
    __syncthreads();
#pragma unroll
    for (int i = threadIdx.y; i < 32; i += 8) {
        float v = t[threadIdx.x][i];
        __nv_bfloat16 h, l;
        bsplit(v, h, l);
        size_t o = (size_t)(c0 + i) * rows + r0 + threadIdx.x;
        ho[o] = h;
        lw[o] = l;
    }
}
// ash[b][g*256+k] = gvals[b,g] * prev[g][b][k], split hi/lo (row-major [b][1024])
__global__ void gacc_prep_k(const float* __restrict__ prev) {
    uint32_t i = blockIdx.x * 256 + threadIdx.x;
    uint32_t e = i * 4, b = e >> 10, gk = e & 1023, g = gk >> 8, k = gk & 255;
    float s = g_gvals[b * 4 + g];
    float4 v = *(const float4*)(prev + ((size_t)g * NBAT + b) * 256 + k);
    v.x *= s; v.y *= s; v.z *= s; v.w *= s;
    __nv_bfloat16 h0, h1, h2, h3, l0, l1, l2, l3;
    bsplit(v.x, h0, l0); bsplit(v.y, h1, l1); bsplit(v.z, h2, l2); bsplit(v.w, h3, l3);
    size_t o = ((size_t)b * 1024 + gk) >> 1;
    ((__nv_bfloat162*)d_ash)[o]     = __nv_bfloat162(h0, h1);
    ((__nv_bfloat162*)d_ash)[o + 1] = __nv_bfloat162(h2, h3);
    ((__nv_bfloat162*)d_asl)[o]     = __nv_bfloat162(l0, l1);
    ((__nv_bfloat162*)d_asl)[o + 1] = __nv_bfloat162(l2, l3);
}

// ======================= warp-MMA split GEMM =======================
struct Sub {
    const __nv_bfloat16 *Ahi, *Alo, *Bhi, *Blo;  // B pre-offset to n0
    int aLen, aK0, bLen;
};
struct Slot {
    Sub sub[4];
    int nsub;
    float* C;            // pre-offset to n0
    int ldc;
    const float* b0;     // pre-offset to n0 (or null)
    const float* b1;
};
struct Params { Slot s[8]; };

#define STAGES 3
#define A_PITCH 80
#define B_PITCH 272
#define A_HALF (128 * A_PITCH)          // 10240
#define B_HALF (32 * B_PITCH)           // 8704
#define STAGEB (2 * A_HALF + 2 * B_HALF)  // 37888
#define SMEMB (STAGES * STAGEB)           // 113664

__global__ void __launch_bounds__(256, 2) gemm_k(const __grid_constant__ Params P) {
    extern __shared__ char sm[];
    const Slot& S = P.s[blockIdx.y];
    const int tid = threadIdx.x;
    const int bm = blockIdx.x * 128;
    const uint32_t sbase = s2u(sm);
    const int nit = S.nsub * 8;

    float acc[4][4][4];
#pragma unroll
    for (int a = 0; a < 4; ++a)
#pragma unroll
        for (int b = 0; b < 4; ++b)
#pragma unroll
            for (int c = 0; c < 4; ++c) acc[a][b][c] = 0.f;

    auto issue = [&](int it) {
        const int st = it % STAGES;
        const int sub = it >> 3, kc = it & 7;
        const Sub& sg = S.sub[sub];
        const uint32_t sa = sbase + st * STAGEB;
        // A: c=0,1 -> hi ; c=2,3 -> lo   (512 x 16B groups per half)
#pragma unroll
        for (int c = 0; c < 4; ++c) {
            int idx = tid + (c & 1) * 256;            // 0..511 within half
            int r = idx >> 2, g = idx & 3;
            const __nv_bfloat16* Ag = (c < 2) ? sg.Ahi : sg.Alo;
            uint32_t dst = sa + ((c < 2) ? 0 : A_HALF) + r * A_PITCH + g * 16;
            cp16(dst, Ag + (size_t)(bm + r) * sg.aLen + sg.aK0 + kc * 32 + g * 8);
        }
        // B: [k][n] rows; c=0,1 -> hi ; c=2,3 -> lo  (512 groups per half)
#pragma unroll
        for (int c = 0; c < 4; ++c) {
            int idx = tid + (c & 1) * 256;
            int k = idx >> 4, gg = idx & 15;
            const __nv_bfloat16* Bg = (c < 2) ? sg.Bhi : sg.Blo;
            uint32_t dst = sa + 2 * A_HALF + ((c < 2) ? 0 : B_HALF) + k * B_PITCH + gg * 16;
            cp16(dst, Bg + (size_t)(kc * 32 + k) * sg.bLen + gg * 8);
        }
        cp_commit();
    };

    issue(0);
    issue(1);

    const int wid = tid >> 5, lane = tid & 31;
    const int wm = wid >> 2, wn = wid & 3;

    for (int it = 0; it < nit; ++it) {
        cp_wait<STAGES - 2>();
        __syncthreads();
        const uint32_t sa = sbase + (it % STAGES) * STAGEB;
#pragma unroll
        for (int p = 0; p < 3; ++p) {
            const uint32_t aBase = sa + ((p == 1) ? A_HALF : 0);
            const uint32_t bBase = sa + 2 * A_HALF + ((p == 2) ? B_HALF : 0);
#pragma unroll
            for (int kh = 0; kh < 2; ++kh) {
                uint32_t af[4][4];
#pragma unroll
                for (int mi = 0; mi < 4; ++mi) {
                    int row = wm * 64 + mi * 16 + (lane & 15);
                    ldsm4(af[mi], aBase + row * A_PITCH + (kh * 2 + (lane >> 4)) * 16);
                }
                uint32_t bf[4][2];
#pragma unroll
                for (int j = 0; j < 2; ++j) {
                    int g4 = lane >> 3;
                    int krow = kh * 16 + (g4 & 1) * 8 + (lane & 7);
                    int gcol = (wn * 32 + j * 16 + (g4 >> 1) * 8) >> 3;
                    uint32_t r[4];
                    ldsm4t(r, bBase + krow * B_PITCH + gcol * 16);
                    bf[2 * j][0] = r[0]; bf[2 * j][1] = r[1];
                    bf[2 * j + 1][0] = r[2]; bf[2 * j + 1][1] = r[3];
                }
#pragma unroll
                for (int mi = 0; mi < 4; ++mi)
#pragma unroll
                    for (int ni = 0; ni < 4; ++ni) mma16816(acc[mi][ni], af[mi], bf[ni]);
            }
        }
        __syncthreads();
        if (it + STAGES - 1 < nit) issue(it + STAGES - 1);
    }

    // epilogue: direct fp32 stores + bias
#pragma unroll
    for (int mi = 0; mi < 4; ++mi) {
        int r0 = bm + wm * 64 + mi * 16 + (lane >> 2);
#pragma unroll
        for (int ni = 0; ni < 4; ++ni) {
            int col = wn * 32 + ni * 8 + (lane & 3) * 2;
            float bv0 = 0.f, bv1 = 0.f;
            if (S.b0) { bv0 = S.b0[col]; bv1 = S.b0[col + 1]; }
            if (S.b1) { bv0 += S.b1[col]; bv1 += S.b1[col + 1]; }
            float2 v0 = {acc[mi][ni][0] + bv0, acc[mi][ni][1] + bv1};
            float2 v1 = {acc[mi][ni][2] + bv0, acc[mi][ni][3] + bv1};
            *(float2*)(S.C + (size_t)r0 * S.ldc + col) = v0;
            *(float2*)(S.C + (size_t)(r0 + 8) * S.ldc + col) = v1;
        }
    }
}

// ======================= small fp32 kernels (from passing R4 kernel) =======================
__global__ void ug_precompute_k(const float* __restrict__ prev, const float* __restrict__ wug) {
    __shared__ float ws[8 * 1024];
    const int ljbase = blockIdx.y * 8;
    {
        const float4* src = (const float4*)(wug + (size_t)ljbase * 1024);
        float4* dst = (float4*)ws;
#pragma unroll
        for (int i = 0; i < 8; ++i) dst[threadIdx.x + i * 256] = src[threadIdx.x + i * 256];
    }
    __syncthreads();
    const int warp = threadIdx.x >> 5, lane = threadIdx.x & 31;
    const int b = blockIdx.x * 8 + warp;
    float acc[8];
#pragma unroll
    for (int t = 0; t < 8; ++t) acc[t] = 0.f;
#pragma unroll
    for (int g = 0; g < 4; ++g) {
        const float* hrow = prev + ((size_t)g * NBAT + b) * 256;
#pragma unroll
        for (int rr = 0; rr < 8; ++rr) {
            int r = rr * 32 + lane;
            float h = hrow[r];
#pragma unroll
            for (int t = 0; t < 8; ++t) acc[t] += h * ws[t * 1024 + g * 256 + r];
        }
    }
#pragma unroll
    for (int t = 0; t < 8; ++t) {
        float v = acc[t];
#pragma unroll
        for (int o = 16; o > 0; o >>= 1) v += __shfl_xor_sync(0xffffffffu, v, o);
        if (lane == 0) g_ugacc[(size_t)b * 16 + ljbase + t] = v;
    }
}

__global__ void xg_k(const float* __restrict__ xl, const float* __restrict__ wg,
                     const float* __restrict__ bg, const float* __restrict__ bug, int l) {
    __shared__ float ws[1024];
#pragma unroll
    for (int i = 0; i < 4; ++i) ws[threadIdx.x + i * 256] = wg[threadIdx.x + i * 256];
    __syncthreads();
    const int warp = threadIdx.x >> 5, lane = threadIdx.x & 31;
    const int b = blockIdx.x * 8 + warp;
    const float* xrow = xl + (size_t)b * 256;
    float acc[4] = {0.f, 0.f, 0.f, 0.f};
#pragma unroll
    for (int rr = 0; rr < 8; ++rr) {
        int r = rr * 32 + lane;
        float xv = xrow[r];
#pragma unroll
        for (int j = 0; j < 4; ++j) acc[j] += xv * ws[j * 256 + r];
    }
#pragma unroll
    for (int j = 0; j < 4; ++j) {
        float v = acc[j];
#pragma unroll
        for (int o = 16; o > 0; o >>= 1) v += __shfl_xor_sync(0xffffffffu, v, o);
        if (lane == 0)
            g_gvals[b * 4 + j] = tanhf(v + g_ugacc[(size_t)b * 16 + l * 4 + j] + bg[j] + bug[j]);
    }
}

// GRU pointwise + g-weighted b_uij + split h_t into next layer's x operand (row-major)
__global__ void pointwise_k(const float* __restrict__ hprev, const float* __restrict__ buij,
                            float* __restrict__ out) {
    __shared__ float sbu[1024];
#pragma unroll
    for (int i = 0; i < 4; ++i) sbu[threadIdx.x + i * 256] = buij[threadIdx.x + i * 256];
    __syncthreads();
    uint32_t i = blockIdx.x * 256 + threadIdx.x;
    uint32_t b = i >> 7, j = (i & 127) * 2;
    float g0 = g_gvals[b * 4 + 0], g1 = g_gvals[b * 4 + 1];
    float g2 = g_gvals[b * 4 + 2], g3 = g_gvals[b * 4 + 3];
    __nv_bfloat16 hh[2], hl[2];
#pragma unroll
    for (int u = 0; u < 2; ++u) {
        uint32_t r = j + u;
        float zpre = g_zr[(size_t)b * 512 + r];
        float rpre = g_zr[(size_t)b * 512 + 256 + r];
        float z = 1.f / (1.f + expf(-zpre));
        float rt = 1.f / (1.f + expf(-rpre));
        float gt = g_gacc[(size_t)b * 256 + r] + g0 * sbu[r] + g1 * sbu[256 + r] +
                   g2 * sbu[512 + r] + g3 * sbu[768 + r];
        float hc = tanhf(g_cand[(size_t)b * 256 + r] + rt * gt);
        float h = (1.f - z) * hprev[(size_t)b * 256 + r] + z * hc;
        out[(size_t)b * 256 + r] = h;
        bsplit(h, hh[u], hl[u]);
    }
    size_t o = ((size_t)b * 256 + j) >> 1;
    ((__nv_bfloat162*)d_xh)[o] = __nv_bfloat162(hh[0], hh[1]);
    ((__nv_bfloat162*)d_xl)[o] = __nv_bfloat162(hl[0], hl[1]);
}

// ======================= launch =======================
extern "C" void kernel_launch(void* const* d_in, const int* in_sizes, int n_in,
                              void* d_out, int out_size) {
    (void)in_sizes; (void)n_in; (void)out_size;
    const float* x     = (const float*)d_in[0];
    const float* prev  = (const float*)d_in[1];
    const float* w_i2h = (const float*)d_in[2];
    const float* b_i2h = (const float*)d_in[3];
    const float* w_h2h = (const float*)d_in[4];
    const float* b_h2h = (const float*)d_in[5];
    const float* w_j1j = (const float*)d_in[6];
    const float* b_j1j = (const float*)d_in[7];
    const float* w_g   = (const float*)d_in[8];
    const float* b_g   = (const float*)d_in[9];
    const float* w_ug  = (const float*)d_in[10];
    const float* b_ug  = (const float*)d_in[11];
    const float* w_uij = (const float*)d_in[12];
    const float* b_uij = (const float*)d_in[13];
    float* out = (float*)d_out;

    void *xh, *xl, *ph, *pl, *ash, *asl;
    void *wih, *wil, *whh, *whl, *wjh, *wjl, *wuh, *wul;
    void *zrp, *candp, *gaccp;
    cudaGetSymbolAddress(&xh, d_xh);   cudaGetSymbolAddress(&xl, d_xl);
    cudaGetSymbolAddress(&ph, d_ph);   cudaGetSymbolAddress(&pl, d_pl);
    cudaGetSymbolAddress(&ash, d_ash); cudaGetSymbolAddress(&asl, d_asl);
    cudaGetSymbolAddress(&wih, d_wih); cudaGetSymbolAddress(&wil, d_wil);
    cudaGetSymbolAddress(&whh, d_whh); cudaGetSymbolAddress(&whl, d_whl);
    cudaGetSymbolAddress(&wjh, d_wjh); cudaGetSymbolAddress(&wjl, d_wjl);
    cudaGetSymbolAddress(&wuh, d_wuh); cudaGetSymbolAddress(&wul, d_wul);
    cudaGetSymbolAddress(&zrp, g_zr);  cudaGetSymbolAddress(&candp, g_cand);
    cudaGetSymbolAddress(&gaccp, g_gacc);
    cudaFuncSetAttribute(gemm_k, cudaFuncAttributeMaxDynamicSharedMemorySize, SMEMB);

    // ---- upfront operand prep ----
    split_k<<<NBAT * 256 / 1024, 256>>>(x, (__nv_bfloat16*)xh, (__nv_bfloat16*)xl);
    split_k<<<NLAY * NBAT * 256 / 1024, 256>>>(prev, (__nv_bfloat16*)ph, (__nv_bfloat16*)pl);
    prep_w_k<<<dim3(16, 8, 4), dim3(32, 8)>>>(w_i2h, (__nv_bfloat16*)wih, (__nv_bfloat16*)wil, 512);
    prep_w_k<<<dim3(16, 8, 4), dim3(32, 8)>>>(w_h2h, (__nv_bfloat16*)whh, (__nv_bfloat16*)whl, 512);
    prep_w_k<<<dim3(8, 8, 4), dim3(32, 8)>>>(w_j1j, (__nv_bfloat16*)wjh, (__nv_bfloat16*)wjl, 256);
    prep_w_k<<<dim3(8, 8, 16), dim3(32, 8)>>>(w_uij, (__nv_bfloat16*)wuh, (__nv_bfloat16*)wul, 256);
    ug_precompute_k<<<dim3(NBAT / 8, 2), 256>>>(prev, w_ug);

    for (int l = 0; l < NLAY; ++l) {
        const float* xlf = (l == 0) ? x : out + (size_t)(l - 1) * NBAT * NR;
        // global gates (needs x_l fp32; for l>0 pointwise already wrote `out`)
        xg_k<<<NBAT / 8, 256>>>(xlf, w_g + (size_t)l * 1024, b_g + l * 4, b_ug + l * 4, l);
        gacc_prep_k<<<NBAT * 1024 / 1024, 256>>>(prev);

        Params P;
        const __nv_bfloat16* xhi = (const __nv_bfloat16*)xh;
        const __nv_bfloat16* xlo = (const __nv_bfloat16*)xl;
        const __nv_bfloat16* phi = (const __nv_bfloat16*)ph + (size_t)l * NBAT * 256;
        const __nv_bfloat16* plo = (const __nv_bfloat16*)pl + (size_t)l * NBAT * 256;
        // slots 0-3: zr (x@Wi^T + h_l@Wh^T), n0 = 128*s, N=512
        for (int s = 0; s < 4; ++s) {
            Slot& c = P.s[s];
            int n0 = 128 * s;
            c.sub[0] = {xhi, xlo, (const __nv_bfloat16*)wih + (size_t)l * 131072 + n0,
                        (const __nv_bfloat16*)wil + (size_t)l * 131072 + n0, 256, 0, 512};
            c.sub[1] = {phi, plo, (const __nv_bfloat16*)whh + (size_t)l * 131072 + n0,
                        (const __nv_bfloat16*)whl + (size_t)l * 131072 + n0, 256, 0, 512};
            c.nsub = 2; c.C = (float*)zrp + n0; c.ldc = 512;
            c.b0 = b_i2h + (size_t)l * 512 + n0; c.b1 = b_h2h + (size_t)l * 512 + n0;
        }
        // slots 4-5: cand (x@Wj^T), N=256
        for (int s = 4; s < 6; ++s) {
            Slot& c = P.s[s];
            int n0 = 128 * (s - 4);
            c.sub[0] = {xhi, xlo, (const __nv_bfloat16*)wjh + (size_t)l * 65536 + n0,
                        (const __nv_bfloat16*)wjl + (size_t)l * 65536 + n0, 256, 0, 256};
            c.sub[1] = c.sub[0];
            c.nsub = 1; c.C = (float*)candp + n0; c.ldc = 256;
            c.b0 = b_j1j + (size_t)l * 256 + n0; c.b1 = nullptr;
        }
        // slots 6-7: g_acc (4 gated-feedback subs, g-scale folded into A), N=256
        for (int s = 6; s < 8; ++s) {
            Slot& c = P.s[s];
            int n0 = 128 * (s - 6);
            for (int g = 0; g < 4; ++g)
                c.sub[g] = {(const __nv_bfloat16*)ash, (const __nv_bfloat16*)asl,
                            (const __nv_bfloat16*)wuh + ((size_t)l * 4 + g) * 65536 + n0,
                            (const __nv_bfloat16*)wul + ((size_t)l * 4 + g) * 65536 + n0,
                            1024, g * 256, 256};
            c.nsub = 4; c.C = (float*)gaccp + n0; c.ldc = 256;
            c.b0 = nullptr; c.b1 = nullptr;
        }
        gemm_k<<<dim3(NBAT / 128, 8), 256, SMEMB>>>(P);

        pointwise_k<<<NBAT * 128 / 256, 256>>>(prev + (size_t)l * NBAT * NR,
                                               b_uij + (size_t)l * 1024,
                                               out + (size_t)l * NBAT * NR);
    }
}

// round 8
// speedup vs baseline: 2.8233x; 1.2855x over previous
#include <cuda_runtime.h>
#include <cuda_fp16.h>
#include <math.h>
#include <stdint.h>

#define NLAY 4
#define NBAT 16384
#define NR   256

// ======================= device scratch (no runtime alloc) =======================
// Activations, row-major fp16 hi/lo (2-term split; lo captures fp16 rounding residual)
__device__ __align__(16) __half d_xh[(size_t)NBAT * 256], d_xl[(size_t)NBAT * 256];
__device__ __align__(16) __half d_ph[(size_t)NLAY * NBAT * 256], d_pl[(size_t)NLAY * NBAT * 256];
__device__ __align__(16) __half d_ash[(size_t)NBAT * 1024], d_asl[(size_t)NBAT * 1024];
// Weights transposed to [K=256][N] fp16 (hi only — dropped A·deltaB term ~2^-12)
__device__ __align__(16) __half d_wih[(size_t)NLAY * 256 * 512];
__device__ __align__(16) __half d_whh[(size_t)NLAY * 256 * 512];
__device__ __align__(16) __half d_wjh[(size_t)NLAY * 256 * 256];
__device__ __align__(16) __half d_wuh[(size_t)NLAY * 4 * 256 * 256];
// fp32 intermediates
__device__ float g_ugacc[NBAT * 16];
__device__ float g_gvals[NBAT * 4];
__device__ float g_zr[(size_t)NBAT * 2 * NR];
__device__ float g_cand[(size_t)NBAT * NR];
__device__ float g_gacc[(size_t)NBAT * NR];

// ======================= PTX helpers (base sm_100 features only) =======================
__device__ __forceinline__ uint32_t s2u(const void* p) {
    uint32_t a;
    asm("{ .reg .u64 t; cvta.to.shared.u64 t, %1; cvt.u32.u64 %0, t; }" : "=r"(a) : "l"(p));
    return a;
}
__device__ __forceinline__ void cp16(uint32_t dst, const void* src) {
    asm volatile("cp.async.cg.shared.global [%0], [%1], 16;" ::"r"(dst), "l"(src) : "memory");
}
__device__ __forceinline__ void cp_commit() { asm volatile("cp.async.commit_group;" ::: "memory"); }
template <int N>
__device__ __forceinline__ void cp_wait() { asm volatile("cp.async.wait_group %0;" ::"n"(N) : "memory"); }
__device__ __forceinline__ void ldsm4(uint32_t* r, uint32_t a) {
    asm volatile("ldmatrix.sync.aligned.m8n8.x4.shared.b16 {%0,%1,%2,%3}, [%4];"
                 : "=r"(r[0]), "=r"(r[1]), "=r"(r[2]), "=r"(r[3]) : "r"(a));
}
__device__ __forceinline__ void ldsm4t(uint32_t* r, uint32_t a) {
    asm volatile("ldmatrix.sync.aligned.m8n8.x4.trans.shared.b16 {%0,%1,%2,%3}, [%4];"
                 : "=r"(r[0]), "=r"(r[1]), "=r"(r[2]), "=r"(r[3]) : "r"(a));
}
__device__ __forceinline__ void mma16816(float* c, const uint32_t* a, const uint32_t* b) {
    asm volatile(
        "mma.sync.aligned.m16n8k16.row.col.f32.f16.f16.f32 "
        "{%0,%1,%2,%3}, {%4,%5,%6,%7}, {%8,%9}, {%0,%1,%2,%3};"
        : "+f"(c[0]), "+f"(c[1]), "+f"(c[2]), "+f"(c[3])
        : "r"(a[0]), "r"(a[1]), "r"(a[2]), "r"(a[3]), "r"(b[0]), "r"(b[1]));
}
__device__ __forceinline__ void hsplit(float v, __half& h, __half& l) {
    h = __float2half_rn(v);
    l = __float2half_rn(v - __half2float(h));
}

// ======================= prep kernels =======================
// row-major fp32 -> hi/lo fp16 (layout-preserving), 4 elems/thread
__global__ void split_k(const float* __restrict__ src, __half* __restrict__ hi,
                        __half* __restrict__ lo) {
    size_t i = (size_t)blockIdx.x * 256 + threadIdx.x;
    float4 v = ((const float4*)src)[i];
    __half h0, h1, h2, h3, l0, l1, l2, l3;
    hsplit(v.x, h0, l0); hsplit(v.y, h1, l1); hsplit(v.z, h2, l2); hsplit(v.w, h3, l3);
    ((__half2*)hi)[2 * i]     = __halves2half2(h0, h1);
    ((__half2*)hi)[2 * i + 1] = __halves2half2(h2, h3);
    ((__half2*)lo)[2 * i]     = __halves2half2(l0, l1);
    ((__half2*)lo)[2 * i + 1] = __halves2half2(l2, l3);
}
// W [batch][rows][256] fp32 -> Wt [batch][256][rows] fp16 (transpose, hi only)
__global__ void prep_w_k(const float* __restrict__ src, __half* __restrict__ hi, int rows) {
    __shared__ float t[32][33];
    const float* s = src + (size_t)blockIdx.z * rows * 256;
    __half* ho = hi + (size_t)blockIdx.z * rows * 256;
    int r0 = blockIdx.x * 32, c0 = blockIdx.y * 32;
#pragma unroll
    for (int i = threadIdx.y; i < 32; i += 8)
        t[i][threadIdx.x] = s[(size_t)(r0 + i) * 256 + c0 + threadIdx.x];
    __syncthreads();
#pragma unroll
    for (int i = threadIdx.y; i < 32; i += 8) {
        size_t o = (size_t)(c0 + i) * rows + r0 + threadIdx.x;
        ho[o] = __float2half_rn(t[threadIdx.x][i]);
    }
}
// ash[b][g*256+k] = gvals[b,g] * prev[g][b][k], split hi/lo fp16 (row-major [b][1024])
__global__ void gacc_prep_k(const float* __restrict__ prev) {
    uint32_t i = blockIdx.x * 256 + threadIdx.x;
    uint32_t e = i * 4, b = e >> 10, gk = e & 1023, g = gk >> 8, k = gk & 255;
    float s = g_gvals[b * 4 + g];
    float4 v = *(const float4*)(prev + ((size_t)g * NBAT + b) * 256 + k);
    v.x *= s; v.y *= s; v.z *= s; v.w *= s;
    __half h0, h1, h2, h3, l0, l1, l2, l3;
    hsplit(v.x, h0, l0); hsplit(v.y, h1, l1); hsplit(v.z, h2, l2); hsplit(v.w, h3, l3);
    size_t o = ((size_t)b * 1024 + gk) >> 1;
    ((__half2*)d_ash)[o]     = __halves2half2(h0, h1);
    ((__half2*)d_ash)[o + 1] = __halves2half2(h2, h3);
    ((__half2*)d_asl)[o]     = __halves2half2(l0, l1);
    ((__half2*)d_asl)[o + 1] = __halves2half2(l2, l3);
}

// ======================= warp-MMA 2-pass split GEMM =======================
struct Sub {
    const __half *Ahi, *Alo, *Bhi;   // B pre-offset to n0
    int aLen, aK0, bLen;
};
struct Slot {
    Sub sub[4];
    int nsub;
    float* C;            // pre-offset to n0
    int ldc;
    const float* b0;     // pre-offset to n0 (or null)
    const float* b1;
};
struct Params { Slot s[8]; };

#define STAGES 3
#define A_PITCH 80
#define B_PITCH 272
#define A_HALF (128 * A_PITCH)              // 10240
#define B_HALF (32 * B_PITCH)               // 8704
#define STAGEB (2 * A_HALF + B_HALF)        // 29184
#define SMEMB (STAGES * STAGEB)             // 87552

__global__ void __launch_bounds__(256, 2) gemm_k(const __grid_constant__ Params P) {
    extern __shared__ char sm[];
    const Slot& S = P.s[blockIdx.y];
    const int tid = threadIdx.x;
    const int bm = blockIdx.x * 128;
    const uint32_t sbase = s2u(sm);
    const int nit = S.nsub * 8;

    float acc[4][4][4];
#pragma unroll
    for (int a = 0; a < 4; ++a)
#pragma unroll
        for (int b = 0; b < 4; ++b)
#pragma unroll
            for (int c = 0; c < 4; ++c) acc[a][b][c] = 0.f;

    auto issue = [&](int it) {
        const int st = it % STAGES;
        const int sub = it >> 3, kc = it & 7;
        const Sub& sg = S.sub[sub];
        const uint32_t sa = sbase + st * STAGEB;
        // A: c=0,1 -> hi ; c=2,3 -> lo   (512 x 16B groups per half)
#pragma unroll
        for (int c = 0; c < 4; ++c) {
            int idx = tid + (c & 1) * 256;            // 0..511 within half
            int r = idx >> 2, g = idx & 3;
            const __half* Ag = (c < 2) ? sg.Ahi : sg.Alo;
            uint32_t dst = sa + ((c < 2) ? 0 : A_HALF) + r * A_PITCH + g * 16;
            cp16(dst, Ag + (size_t)(bm + r) * sg.aLen + sg.aK0 + kc * 32 + g * 8);
        }
        // B: [k][n] rows, hi only (512 x 16B groups)
#pragma unroll
        for (int c = 0; c < 2; ++c) {
            int idx = tid + c * 256;
            int k = idx >> 4, gg = idx & 15;
            uint32_t dst = sa + 2 * A_HALF + k * B_PITCH + gg * 16;
            cp16(dst, sg.Bhi + (size_t)(kc * 32 + k) * sg.bLen + gg * 8);
        }
        cp_commit();
    };

    issue(0);
    issue(1);

    const int wid = tid >> 5, lane = tid & 31;
    const int wm = wid >> 2, wn = wid & 3;

    for (int it = 0; it < nit; ++it) {
        cp_wait<STAGES - 2>();
        __syncthreads();
        const uint32_t sa = sbase + (it % STAGES) * STAGEB;
        const uint32_t bBase = sa + 2 * A_HALF;
#pragma unroll
        for (int kh = 0; kh < 2; ++kh) {
            // load all fragments for this kh once, reuse across both passes
            uint32_t afh[4][4], afl[4][4];
#pragma unroll
            for (int mi = 0; mi < 4; ++mi) {
                int row = wm * 64 + mi * 16 + (lane & 15);
                int cofs = (kh * 2 + (lane >> 4)) * 16;
                ldsm4(afh[mi], sa + row * A_PITCH + cofs);
                ldsm4(afl[mi], sa + A_HALF + row * A_PITCH + cofs);
            }
            uint32_t bf[4][2];
#pragma unroll
            for (int j = 0; j < 2; ++j) {
                int g4 = lane >> 3;
                int krow = kh * 16 + (g4 & 1) * 8 + (lane & 7);
                int gcol = (wn * 32 + j * 16 + (g4 >> 1) * 8) >> 3;
                uint32_t r[4];
                ldsm4t(r, bBase + krow * B_PITCH + gcol * 16);
                bf[2 * j][0] = r[0]; bf[2 * j][1] = r[1];
                bf[2 * j + 1][0] = r[2]; bf[2 * j + 1][1] = r[3];
            }
#pragma unroll
            for (int mi = 0; mi < 4; ++mi)
#pragma unroll
                for (int ni = 0; ni < 4; ++ni) mma16816(acc[mi][ni], afh[mi], bf[ni]);
#pragma unroll
            for (int mi = 0; mi < 4; ++mi)
#pragma unroll
                for (int ni = 0; ni < 4; ++ni) mma16816(acc[mi][ni], afl[mi], bf[ni]);
        }
        __syncthreads();
        if (it + STAGES - 1 < nit) issue(it + STAGES - 1);
    }

    // epilogue: direct fp32 stores + bias
#pragma unroll
    for (int mi = 0; mi < 4; ++mi) {
        int r0 = bm + wm * 64 + mi * 16 + (lane >> 2);
#pragma unroll
        for (int ni = 0; ni < 4; ++ni) {
            int col = wn * 32 + ni * 8 + (lane & 3) * 2;
            float bv0 = 0.f, bv1 = 0.f;
            if (S.b0) { bv0 = S.b0[col]; bv1 = S.b0[col + 1]; }
            if (S.b1) { bv0 += S.b1[col]; bv1 += S.b1[col + 1]; }
            float2 v0 = {acc[mi][ni][0] + bv0, acc[mi][ni][1] + bv1};
            float2 v1 = {acc[mi][ni][2] + bv0, acc[mi][ni][3] + bv1};
            *(float2*)(S.C + (size_t)r0 * S.ldc + col) = v0;
            *(float2*)(S.C + (size_t)(r0 + 8) * S.ldc + col) = v1;
        }
    }
}

// ======================= small fp32 kernels =======================
__global__ void ug_precompute_k(const float* __restrict__ prev, const float* __restrict__ wug) {
    __shared__ float ws[8 * 1024];
    const int ljbase = blockIdx.y * 8;
    {
        const float4* src = (const float4*)(wug + (size_t)ljbase * 1024);
        float4* dst = (float4*)ws;
#pragma unroll
        for (int i = 0; i < 8; ++i) dst[threadIdx.x + i * 256] = src[threadIdx.x + i * 256];
    }
    __syncthreads();
    const int warp = threadIdx.x >> 5, lane = threadIdx.x & 31;
    const int b = blockIdx.x * 8 + warp;
    float acc[8];
#pragma unroll
    for (int t = 0; t < 8; ++t) acc[t] = 0.f;
#pragma unroll
    for (int g = 0; g < 4; ++g) {
        const float* hrow = prev + ((size_t)g * NBAT + b) * 256;
#pragma unroll
        for (int rr = 0; rr < 8; ++rr) {
            int r = rr * 32 + lane;
            float h = hrow[r];
#pragma unroll
            for (int t = 0; t < 8; ++t) acc[t] += h * ws[t * 1024 + g * 256 + r];
        }
    }
#pragma unroll
    for (int t = 0; t < 8; ++t) {
        float v = acc[t];
#pragma unroll
        for (int o = 16; o > 0; o >>= 1) v += __shfl_xor_sync(0xffffffffu, v, o);
        if (lane == 0) g_ugacc[(size_t)b * 16 + ljbase + t] = v;
    }
}

__global__ void xg_k(const float* __restrict__ xl, const float* __restrict__ wg,
                     const float* __restrict__ bg, const float* __restrict__ bug, int l) {
    __shared__ float ws[1024];
#pragma unroll
    for (int i = 0; i < 4; ++i) ws[threadIdx.x + i * 256] = wg[threadIdx.x + i * 256];
    __syncthreads();
    const int warp = threadIdx.x >> 5, lane = threadIdx.x & 31;
    const int b = blockIdx.x * 8 + warp;
    const float* xrow = xl + (size_t)b * 256;
    float acc[4] = {0.f, 0.f, 0.f, 0.f};
#pragma unroll
    for (int rr = 0; rr < 8; ++rr) {
        int r = rr * 32 + lane;
        float xv = xrow[r];
#pragma unroll
        for (int j = 0; j < 4; ++j) acc[j] += xv * ws[j * 256 + r];
    }
#pragma unroll
    for (int j = 0; j < 4; ++j) {
        float v = acc[j];
#pragma unroll
        for (int o = 16; o > 0; o >>= 1) v += __shfl_xor_sync(0xffffffffu, v, o);
        if (lane == 0)
            g_gvals[b * 4 + j] = tanhf(v + g_ugacc[(size_t)b * 16 + l * 4 + j] + bg[j] + bug[j]);
    }
}

// GRU pointwise + g-weighted b_uij + split h_t into next layer's x operand (row-major fp16)
__global__ void pointwise_k(const float* __restrict__ hprev, const float* __restrict__ buij,
                            float* __restrict__ out) {
    __shared__ float sbu[1024];
#pragma unroll
    for (int i = 0; i < 4; ++i) sbu[threadIdx.x + i * 256] = buij[threadIdx.x + i * 256];
    __syncthreads();
    uint32_t i = blockIdx.x * 256 + threadIdx.x;
    uint32_t b = i >> 7, j = (i & 127) * 2;
    float g0 = g_gvals[b * 4 + 0], g1 = g_gvals[b * 4 + 1];
    float g2 = g_gvals[b * 4 + 2], g3 = g_gvals[b * 4 + 3];
    __half hh[2], hl[2];
#pragma unroll
    for (int u = 0; u < 2; ++u) {
        uint32_t r = j + u;
        float zpre = g_zr[(size_t)b * 512 + r];
        float rpre = g_zr[(size_t)b * 512 + 256 + r];
        float z = 1.f / (1.f + expf(-zpre));
        float rt = 1.f / (1.f + expf(-rpre));
        float gt = g_gacc[(size_t)b * 256 + r] + g0 * sbu[r] + g1 * sbu[256 + r] +
                   g2 * sbu[512 + r] + g3 * sbu[768 + r];
        float hc = tanhf(g_cand[(size_t)b * 256 + r] + rt * gt);
        float h = (1.f - z) * hprev[(size_t)b * 256 + r] + z * hc;
        out[(size_t)b * 256 + r] = h;
        hsplit(h, hh[u], hl[u]);
    }
    size_t o = ((size_t)b * 256 + j) >> 1;
    ((__half2*)d_xh)[o] = __halves2half2(hh[0], hh[1]);
    ((__half2*)d_xl)[o] = __halves2half2(hl[0], hl[1]);
}

// ======================= launch =======================
extern "C" void kernel_launch(void* const* d_in, const int* in_sizes, int n_in,
                              void* d_out, int out_size) {
    (void)in_sizes; (void)n_in; (void)out_size;
    const float* x     = (const float*)d_in[0];
    const float* prev  = (const float*)d_in[1];
    const float* w_i2h = (const float*)d_in[2];
    const float* b_i2h = (const float*)d_in[3];
    const float* w_h2h = (const float*)d_in[4];
    const float* b_h2h = (const float*)d_in[5];
    const float* w_j1j = (const float*)d_in[6];
    const float* b_j1j = (const float*)d_in[7];
    const float* w_g   = (const float*)d_in[8];
    const float* b_g   = (const float*)d_in[9];
    const float* w_ug  = (const float*)d_in[10];
    const float* b_ug  = (const float*)d_in[11];
    const float* w_uij = (const float*)d_in[12];
    const float* b_uij = (const float*)d_in[13];
    float* out = (float*)d_out;

    void *xh, *xl, *ph, *pl, *ash, *asl;
    void *wih, *whh, *wjh, *wuh;
    void *zrp, *candp, *gaccp;
    cudaGetSymbolAddress(&xh, d_xh);   cudaGetSymbolAddress(&xl, d_xl);
    cudaGetSymbolAddress(&ph, d_ph);   cudaGetSymbolAddress(&pl, d_pl);
    cudaGetSymbolAddress(&ash, d_ash); cudaGetSymbolAddress(&asl, d_asl);
    cudaGetSymbolAddress(&wih, d_wih); cudaGetSymbolAddress(&whh, d_whh);
    cudaGetSymbolAddress(&wjh, d_wjh); cudaGetSymbolAddress(&wuh, d_wuh);
    cudaGetSymbolAddress(&zrp, g_zr);  cudaGetSymbolAddress(&candp, g_cand);
    cudaGetSymbolAddress(&gaccp, g_gacc);
    cudaFuncSetAttribute(gemm_k, cudaFuncAttributeMaxDynamicSharedMemorySize, SMEMB);

    // ---- upfront operand prep ----
    split_k<<<NBAT * 256 / 1024, 256>>>(x, (__half*)xh, (__half*)xl);
    split_k<<<NLAY * NBAT * 256 / 1024, 256>>>(prev, (__half*)ph, (__half*)pl);
    prep_w_k<<<dim3(16, 8, 4), dim3(32, 8)>>>(w_i2h, (__half*)wih, 512);
    prep_w_k<<<dim3(16, 8, 4), dim3(32, 8)>>>(w_h2h, (__half*)whh, 512);
    prep_w_k<<<dim3(8, 8, 4), dim3(32, 8)>>>(w_j1j, (__half*)wjh, 256);
    prep_w_k<<<dim3(8, 8, 16), dim3(32, 8)>>>(w_uij, (__half*)wuh, 256);
    ug_precompute_k<<<dim3(NBAT / 8, 2), 256>>>(prev, w_ug);

    for (int l = 0; l < NLAY; ++l) {
        const float* xlf = (l == 0) ? x : out + (size_t)(l - 1) * NBAT * NR;
        xg_k<<<NBAT / 8, 256>>>(xlf, w_g + (size_t)l * 1024, b_g + l * 4, b_ug + l * 4, l);
        gacc_prep_k<<<NBAT * 1024 / 1024, 256>>>(prev);

        Params P;
        const __half* xhi = (const __half*)xh;
        const __half* xlo = (const __half*)xl;
        const __half* phi = (const __half*)ph + (size_t)l * NBAT * 256;
        const __half* plo = (const __half*)pl + (size_t)l * NBAT * 256;
        // slots 0-3: zr (x@Wi^T + h_l@Wh^T), n0 = 128*s, N=512
        for (int s = 0; s < 4; ++s) {
            Slot& c = P.s[s];
            int n0 = 128 * s;
            c.sub[0] = {xhi, xlo, (const __half*)wih + (size_t)l * 131072 + n0, 256, 0, 512};
            c.sub[1] = {phi, plo, (const __half*)whh + (size_t)l * 131072 + n0, 256, 0, 512};
            c.nsub = 2; c.C = (float*)zrp + n0; c.ldc = 512;
            c.b0 = b_i2h + (size_t)l * 512 + n0; c.b1 = b_h2h + (size_t)l * 512 + n0;
        }
        // slots 4-5: cand (x@Wj^T), N=256
        for (int s = 4; s < 6; ++s) {
            Slot& c = P.s[s];
            int n0 = 128 * (s - 4);
            c.sub[0] = {xhi, xlo, (const __half*)wjh + (size_t)l * 65536 + n0, 256, 0, 256};
            c.sub[1] = c.sub[0];
            c.nsub = 1; c.C = (float*)candp + n0; c.ldc = 256;
            c.b0 = b_j1j + (size_t)l * 256 + n0; c.b1 = nullptr;
        }
        // slots 6-7: g_acc (4 gated-feedback subs, g-scale folded into A), N=256
        for (int s = 6; s < 8; ++s) {
            Slot& c = P.s[s];
            int n0 = 128 * (s - 6);
            for (int g = 0; g < 4; ++g)
                c.sub[g] = {(const __half*)ash, (const __half*)asl,
                            (const __half*)wuh + ((size_t)l * 4 + g) * 65536 + n0,
                            1024, g * 256, 256};
            c.nsub = 4; c.C = (float*)gaccp + n0; c.ldc = 256;
            c.b0 = nullptr; c.b1 = nullptr;
        }
        gemm_k<<<dim3(NBAT / 128, 8), 256, SMEMB>>>(P);

        pointwise_k<<<NBAT * 128 / 256, 256>>>(prev + (size_t)l * NBAT * NR,
                                               b_uij + (size_t)l * 1024,
                                               out + (size_t)l * NBAT * NR);
    }
}

// round 11
// speedup vs baseline: 2.8644x; 1.0146x over previous
#include <cuda_runtime.h>
#include <cuda_fp16.h>
#include <math.h>
#include <stdint.h>

#define NLAY 4
#define NBAT 16384
#define NR   256

// ======================= device scratch (no runtime alloc) =======================
// Activations, row-major fp16 hi/lo (2-term split; lo captures fp16 rounding residual)
__device__ __align__(16) __half d_xh[(size_t)NBAT * 256], d_xl[(size_t)NBAT * 256];
__device__ __align__(16) __half d_ph[(size_t)NLAY * NBAT * 256], d_pl[(size_t)NLAY * NBAT * 256];
__device__ __align__(16) __half d_ash[(size_t)NBAT * 1024], d_asl[(size_t)NBAT * 1024];
// Weights transposed to [K=256][N] fp16 (hi only — dropped A·deltaB term)
__device__ __align__(16) __half d_wih[(size_t)NLAY * 256 * 512];
__device__ __align__(16) __half d_whh[(size_t)NLAY * 256 * 512];
__device__ __align__(16) __half d_wjh[(size_t)NLAY * 256 * 256];
__device__ __align__(16) __half d_wuh[(size_t)NLAY * 4 * 256 * 256];
// fp32 intermediates
__device__ float g_ugacc[NBAT * 16];
__device__ float g_gvals[NBAT * 4];
__device__ float g_zr[(size_t)NBAT * 2 * NR];
__device__ float g_cand[(size_t)NBAT * NR];
__device__ float g_gacc[(size_t)NBAT * NR];     // partial: g=0,1
__device__ float g_gacc2[(size_t)NBAT * NR];    // partial: g=2,3

// ======================= PTX helpers (base sm_100 features only) =======================
__device__ __forceinline__ uint32_t s2u(const void* p) {
    uint32_t a;
    asm("{ .reg .u64 t; cvta.to.shared.u64 t, %1; cvt.u32.u64 %0, t; }" : "=r"(a) : "l"(p));
    return a;
}
__device__ __forceinline__ void cp16(uint32_t dst, const void* src) {
    asm volatile("cp.async.cg.shared.global [%0], [%1], 16;" ::"r"(dst), "l"(src) : "memory");
}
__device__ __forceinline__ void cp_commit() { asm volatile("cp.async.commit_group;" ::: "memory"); }
template <int N>
__device__ __forceinline__ void cp_wait() { asm volatile("cp.async.wait_group %0;" ::"n"(N) : "memory"); }
__device__ __forceinline__ void ldsm4(uint32_t* r, uint32_t a) {
    asm volatile("ldmatrix.sync.aligned.m8n8.x4.shared.b16 {%0,%1,%2,%3}, [%4];"
                 : "=r"(r[0]), "=r"(r[1]), "=r"(r[2]), "=r"(r[3]) : "r"(a));
}
__device__ __forceinline__ void ldsm4t(uint32_t* r, uint32_t a) {
    asm volatile("ldmatrix.sync.aligned.m8n8.x4.trans.shared.b16 {%0,%1,%2,%3}, [%4];"
                 : "=r"(r[0]), "=r"(r[1]), "=r"(r[2]), "=r"(r[3]) : "r"(a));
}
__device__ __forceinline__ void mma16816(float* c, const uint32_t* a, const uint32_t* b) {
    asm volatile(
        "mma.sync.aligned.m16n8k16.row.col.f32.f16.f16.f32 "
        "{%0,%1,%2,%3}, {%4,%5,%6,%7}, {%8,%9}, {%0,%1,%2,%3};"
        : "+f"(c[0]), "+f"(c[1]), "+f"(c[2]), "+f"(c[3])
        : "r"(a[0]), "r"(a[1]), "r"(a[2]), "r"(a[3]), "r"(b[0]), "r"(b[1]));
}
__device__ __forceinline__ void hsplit(float v, __half& h, __half& l) {
    h = __float2half_rn(v);
    l = __float2half_rn(v - __half2float(h));
}

// ======================= prep kernels =======================
__global__ void split_k(const float* __restrict__ src, __half* __restrict__ hi,
                        __half* __restrict__ lo) {
    size_t i = (size_t)blockIdx.x * 256 + threadIdx.x;
    float4 v = ((const float4*)src)[i];
    __half h0, h1, h2, h3, l0, l1, l2, l3;
    hsplit(v.x, h0, l0); hsplit(v.y, h1, l1); hsplit(v.z, h2, l2); hsplit(v.w, h3, l3);
    ((__half2*)hi)[2 * i]     = __halves2half2(h0, h1);
    ((__half2*)hi)[2 * i + 1] = __halves2half2(h2, h3);
    ((__half2*)lo)[2 * i]     = __halves2half2(l0, l1);
    ((__half2*)lo)[2 * i + 1] = __halves2half2(l2, l3);
}
// W [batch][rows][256] fp32 -> Wt [batch][256][rows] fp16 (transpose, hi only)
__global__ void prep_w_k(const float* __restrict__ src, __half* __restrict__ hi, int rows) {
    __shared__ float t[32][33];
    const float* s = src + (size_t)blockIdx.z * rows * 256;
    __half* ho = hi + (size_t)blockIdx.z * rows * 256;
    int r0 = blockIdx.x * 32, c0 = blockIdx.y * 32;
#pragma unroll
    for (int i = threadIdx.y; i < 32; i += 8)
        t[i][threadIdx.x] = s[(size_t)(r0 + i) * 256 + c0 + threadIdx.x];
    __syncthreads();
#pragma unroll
    for (int i = threadIdx.y; i < 32; i += 8) {
        size_t o = (size_t)(c0 + i) * rows + r0 + threadIdx.x;
        ho[o] = __float2half_rn(t[threadIdx.x][i]);
    }
}
// ash[b][g*256+k] = gvals[b,g] * prev[g][b][k], split hi/lo fp16 (row-major [b][1024])
__global__ void gacc_prep_k(const float* __restrict__ prev) {
    uint32_t i = blockIdx.x * 256 + threadIdx.x;
    uint32_t e = i * 4, b = e >> 10, gk = e & 1023, g = gk >> 8, k = gk & 255;
    float s = g_gvals[b * 4 + g];
    float4 v = *(const float4*)(prev + ((size_t)g * NBAT + b) * 256 + k);
    v.x *= s; v.y *= s; v.z *= s; v.w *= s;
    __half h0, h1, h2, h3, l0, l1, l2, l3;
    hsplit(v.x, h0, l0); hsplit(v.y, h1, l1); hsplit(v.z, h2, l2); hsplit(v.w, h3, l3);
    size_t o = ((size_t)b * 1024 + gk) >> 1;
    ((__half2*)d_ash)[o]     = __halves2half2(h0, h1);
    ((__half2*)d_ash)[o + 1] = __halves2half2(h2, h3);
    ((__half2*)d_asl)[o]     = __halves2half2(l0, l1);
    ((__half2*)d_asl)[o + 1] = __halves2half2(l2, l3);
}

// ======================= warp-MMA 2-pass split GEMM =======================
struct Sub {
    const __half *Ahi, *Alo, *Bhi;   // B pre-offset to n0
    int aLen, aK0, bLen;
};
struct Slot {
    Sub sub[4];
    int nsub;
    float* C;            // pre-offset to n0
    int ldc;
    const float* b0;     // pre-offset to n0 (or null)
    const float* b1;
};
struct Params { Slot s[10]; };

#define STAGES 3
#define A_PITCH 80
#define B_PITCH 272
#define A_HALF (128 * A_PITCH)              // 10240
#define B_HALF (32 * B_PITCH)               // 8704
#define STAGEB (2 * A_HALF + B_HALF)        // 29184
#define SMEMB (STAGES * STAGEB)             // 87552

__global__ void __launch_bounds__(256, 2) gemm_k(const __grid_constant__ Params P) {
    extern __shared__ char sm[];
    const Slot& S = P.s[blockIdx.y];
    const int tid = threadIdx.x;
    const int bm = blockIdx.x * 128;
    const uint32_t sbase = s2u(sm);
    const int nit = S.nsub * 8;

    float acc[4][4][4];
#pragma unroll
    for (int a = 0; a < 4; ++a)
#pragma unroll
        for (int b = 0; b < 4; ++b)
#pragma unroll
            for (int c = 0; c < 4; ++c) acc[a][b][c] = 0.f;

    auto issue = [&](int it) {
        const int st = it % STAGES;
        const int sub = it >> 3, kc = it & 7;
        const Sub& sg = S.sub[sub];
        const uint32_t sa = sbase + st * STAGEB;
        // A: c=0,1 -> hi ; c=2,3 -> lo   (512 x 16B groups per half)
#pragma unroll
        for (int c = 0; c < 4; ++c) {
            int idx = tid + (c & 1) * 256;
            int r = idx >> 2, g = idx & 3;
            const __half* Ag = (c < 2) ? sg.Ahi : sg.Alo;
            uint32_t dst = sa + ((c < 2) ? 0 : A_HALF) + r * A_PITCH + g * 16;
            cp16(dst, Ag + (size_t)(bm + r) * sg.aLen + sg.aK0 + kc * 32 + g * 8);
        }
        // B: [k][n] rows (hi only)
#pragma unroll
        for (int c = 0; c < 2; ++c) {
            int idx = tid + c * 256;
            int k = idx >> 4, gg = idx & 15;
            uint32_t dst = sa + 2 * A_HALF + k * B_PITCH + gg * 16;
            cp16(dst, sg.Bhi + (size_t)(kc * 32 + k) * sg.bLen + gg * 8);
        }
        cp_commit();
    };

    issue(0);
    issue(1);

    const int wid = tid >> 5, lane = tid & 31;
    const int wm = wid >> 2, wn = wid & 3;

    for (int it = 0; it < nit; ++it) {
        cp_wait<STAGES - 2>();
        __syncthreads();
        const uint32_t sa = sbase + (it % STAGES) * STAGEB;
        const uint32_t bBase = sa + 2 * A_HALF;
#pragma unroll
        for (int kh = 0; kh < 2; ++kh) {
            uint32_t afh[4][4], afl[4][4];
#pragma unroll
            for (int mi = 0; mi < 4; ++mi) {
                int row = wm * 64 + mi * 16 + (lane & 15);
                int cofs = (kh * 2 + (lane >> 4)) * 16;
                ldsm4(afh[mi], sa + row * A_PITCH + cofs);
                ldsm4(afl[mi], sa + A_HALF + row * A_PITCH + cofs);
            }
            uint32_t bf[4][2];
#pragma unroll
            for (int j = 0; j < 2; ++j) {
                int g4 = lane >> 3;
                int krow = kh * 16 + (g4 & 1) * 8 + (lane & 7);
                int gcol = (wn * 32 + j * 16 + (g4 >> 1) * 8) >> 3;
                uint32_t r[4];
                ldsm4t(r, bBase + krow * B_PITCH + gcol * 16);
                bf[2 * j][0] = r[0]; bf[2 * j][1] = r[1];
                bf[2 * j + 1][0] = r[2]; bf[2 * j + 1][1] = r[3];
            }
#pragma unroll
            for (int mi = 0; mi < 4; ++mi)
#pragma unroll
                for (int ni = 0; ni < 4; ++ni) mma16816(acc[mi][ni], afh[mi], bf[ni]);
#pragma unroll
            for (int mi = 0; mi < 4; ++mi)
#pragma unroll
                for (int ni = 0; ni < 4; ++ni) mma16816(acc[mi][ni], afl[mi], bf[ni]);
        }
        __syncthreads();
        if (it + STAGES - 1 < nit) issue(it + STAGES - 1);
    }

    // epilogue: direct fp32 stores + bias
#pragma unroll
    for (int mi = 0; mi < 4; ++mi) {
        int r0 = bm + wm * 64 + mi * 16 + (lane >> 2);
#pragma unroll
        for (int ni = 0; ni < 4; ++ni) {
            int col = wn * 32 + ni * 8 + (lane & 3) * 2;
            float bv0 = 0.f, bv1 = 0.f;
            if (S.b0) { bv0 = S.b0[col]; bv1 = S.b0[col + 1]; }
            if (S.b1) { bv0 += S.b1[col]; bv1 += S.b1[col + 1]; }
            float2 v0 = {acc[mi][ni][0] + bv0, acc[mi][ni][1] + bv1};
            float2 v1 = {acc[mi][ni][2] + bv0, acc[mi][ni][3] + bv1};
            *(float2*)(S.C + (size_t)r0 * S.ldc + col) = v0;
            *(float2*)(S.C + (size_t)(r0 + 8) * S.ldc + col) = v1;
        }
    }
}

// ======================= small fp32 kernels =======================
__global__ void ug_precompute_k(const float* __restrict__ prev, const float* __restrict__ wug) {
    __shared__ float ws[8 * 1024];
    const int ljbase = blockIdx.y * 8;
    {
        const float4* src = (const float4*)(wug + (size_t)ljbase * 1024);
        float4* dst = (float4*)ws;
#pragma unroll
        for (int i = 0; i < 8; ++i) dst[threadIdx.x + i * 256] = src[threadIdx.x + i * 256];
    }
    __syncthreads();
    const int warp = threadIdx.x >> 5, lane = threadIdx.x & 31;
    const int b = blockIdx.x * 8 + warp;
    float acc[8];
#pragma unroll
    for (int t = 0; t < 8; ++t) acc[t] = 0.f;
#pragma unroll
    for (int g = 0; g < 4; ++g) {
        const float* hrow = prev + ((size_t)g * NBAT + b) * 256;
#pragma unroll
        for (int rr = 0; rr < 8; ++rr) {
            int r = rr * 32 + lane;
            float h = hrow[r];
#pragma unroll
            for (int t = 0; t < 8; ++t) acc[t] += h * ws[t * 1024 + g * 256 + r];
        }
    }
#pragma unroll
    for (int t = 0; t < 8; ++t) {
        float v = acc[t];
#pragma unroll
        for (int o = 16; o > 0; o >>= 1) v += __shfl_xor_sync(0xffffffffu, v, o);
        if (lane == 0) g_ugacc[(size_t)b * 16 + ljbase + t] = v;
    }
}

__global__ void xg_k(const float* __restrict__ xl, const float* __restrict__ wg,
                     const float* __restrict__ bg, const float* __restrict__ bug, int l) {
    __shared__ float ws[1024];
#pragma unroll
    for (int i = 0; i < 4; ++i) ws[threadIdx.x + i * 256] = wg[threadIdx.x + i * 256];
    __syncthreads();
    const int warp = threadIdx.x >> 5, lane = threadIdx.x & 31;
    const int b = blockIdx.x * 8 + warp;
    const float* xrow = xl + (size_t)b * 256;
    float acc[4] = {0.f, 0.f, 0.f, 0.f};
#pragma unroll
    for (int rr = 0; rr < 8; ++rr) {
        int r = rr * 32 + lane;
        float xv = xrow[r];
#pragma unroll
        for (int j = 0; j < 4; ++j) acc[j] += xv * ws[j * 256 + r];
    }
#pragma unroll
    for (int j = 0; j < 4; ++j) {
        float v = acc[j];
#pragma unroll
        for (int o = 16; o > 0; o >>= 1) v += __shfl_xor_sync(0xffffffffu, v, o);
        if (lane == 0)
            g_gvals[b * 4 + j] = tanhf(v + g_ugacc[(size_t)b * 16 + l * 4 + j] + bg[j] + bug[j]);
    }
}

// GRU pointwise: gacc = partialA + partialB (+ g-weighted b_uij); split h_t for next layer
__global__ void pointwise_k(const float* __restrict__ hprev, const float* __restrict__ buij,
                            float* __restrict__ out) {
    __shared__ float sbu[1024];
#pragma unroll
    for (int i = 0; i < 4; ++i) sbu[threadIdx.x + i * 256] = buij[threadIdx.x + i * 256];
    __syncthreads();
    uint32_t i = blockIdx.x * 256 + threadIdx.x;
    uint32_t b = i >> 7, j = (i & 127) * 2;
    float g0 = g_gvals[b * 4 + 0], g1 = g_gvals[b * 4 + 1];
    float g2 = g_gvals[b * 4 + 2], g3 = g_gvals[b * 4 + 3];
    __half hh[2], hl[2];
#pragma unroll
    for (int u = 0; u < 2; ++u) {
        uint32_t r = j + u;
        float zpre = g_zr[(size_t)b * 512 + r];
        float rpre = g_zr[(size_t)b * 512 + 256 + r];
        float z = 1.f / (1.f + expf(-zpre));
        float rt = 1.f / (1.f + expf(-rpre));
        size_t br = (size_t)b * 256 + r;
        float gt = g_gacc[br] + g_gacc2[br] + g0 * sbu[r] + g1 * sbu[256 + r] +
                   g2 * sbu[512 + r] + g3 * sbu[768 + r];
        float hc = tanhf(g_cand[br] + rt * gt);
        float h = (1.f - z) * hprev[br] + z * hc;
        out[br] = h;
        hsplit(h, hh[u], hl[u]);
    }
    size_t o = ((size_t)b * 256 + j) >> 1;
    ((__half2*)d_xh)[o] = __halves2half2(hh[0], hh[1]);
    ((__half2*)d_xl)[o] = __halves2half2(hl[0], hl[1]);
}

// ======================= launch =======================
extern "C" void kernel_launch(void* const* d_in, const int* in_sizes, int n_in,
                              void* d_out, int out_size) {
    (void)in_sizes; (void)n_in; (void)out_size;
    const float* x     = (const float*)d_in[0];
    const float* prev  = (const float*)d_in[1];
    const float* w_i2h = (const float*)d_in[2];
    const float* b_i2h = (const float*)d_in[3];
    const float* w_h2h = (const float*)d_in[4];
    const float* b_h2h = (const float*)d_in[5];
    const float* w_j1j = (const float*)d_in[6];
    const float* b_j1j = (const float*)d_in[7];
    const float* w_g   = (const float*)d_in[8];
    const float* b_g   = (const float*)d_in[9];
    const float* w_ug  = (const float*)d_in[10];
    const float* b_ug  = (const float*)d_in[11];
    const float* w_uij = (const float*)d_in[12];
    const float* b_uij = (const float*)d_in[13];
    float* out = (float*)d_out;

    void *xh, *xl, *ph, *pl, *ash, *asl;
    void *wih, *whh, *wjh, *wuh;
    void *zrp, *candp, *gaccp, *gaccp2;
    cudaGetSymbolAddress(&xh, d_xh);   cudaGetSymbolAddress(&xl, d_xl);
    cudaGetSymbolAddress(&ph, d_ph);   cudaGetSymbolAddress(&pl, d_pl);
    cudaGetSymbolAddress(&ash, d_ash); cudaGetSymbolAddress(&asl, d_asl);
    cudaGetSymbolAddress(&wih, d_wih); cudaGetSymbolAddress(&whh, d_whh);
    cudaGetSymbolAddress(&wjh, d_wjh); cudaGetSymbolAddress(&wuh, d_wuh);
    cudaGetSymbolAddress(&zrp, g_zr);  cudaGetSymbolAddress(&candp, g_cand);
    cudaGetSymbolAddress(&gaccp, g_gacc); cudaGetSymbolAddress(&gaccp2, g_gacc2);
    cudaFuncSetAttribute(gemm_k, cudaFuncAttributeMaxDynamicSharedMemorySize, SMEMB);

    // ---- upfront operand prep ----
    split_k<<<NBAT * 256 / 1024, 256>>>(x, (__half*)xh, (__half*)xl);
    split_k<<<NLAY * NBAT * 256 / 1024, 256>>>(prev, (__half*)ph, (__half*)pl);
    prep_w_k<<<dim3(16, 8, 4), dim3(32, 8)>>>(w_i2h, (__half*)wih, 512);
    prep_w_k<<<dim3(16, 8, 4), dim3(32, 8)>>>(w_h2h, (__half*)whh, 512);
    prep_w_k<<<dim3(8, 8, 4), dim3(32, 8)>>>(w_j1j, (__half*)wjh, 256);
    prep_w_k<<<dim3(8, 8, 16), dim3(32, 8)>>>(w_uij, (__half*)wuh, 256);
    ug_precompute_k<<<dim3(NBAT / 8, 2), 256>>>(prev, w_ug);

    for (int l = 0; l < NLAY; ++l) {
        const float* xlf = (l == 0) ? x : out + (size_t)(l - 1) * NBAT * NR;
        xg_k<<<NBAT / 8, 256>>>(xlf, w_g + (size_t)l * 1024, b_g + l * 4, b_ug + l * 4, l);
        gacc_prep_k<<<NBAT * 1024 / 1024, 256>>>(prev);

        Params P;
        const __half* xhi = (const __half*)xh;
        const __half* xlo = (const __half*)xl;
        const __half* phi = (const __half*)ph + (size_t)l * NBAT * 256;
        const __half* plo = (const __half*)pl + (size_t)l * NBAT * 256;
        // slots 0-3: zr (x@Wi^T + h_l@Wh^T), n0 = 128*s, N=512, nit=16
        for (int s = 0; s < 4; ++s) {
            Slot& c = P.s[s];
            int n0 = 128 * s;
            c.sub[0] = {xhi, xlo, (const __half*)wih + (size_t)l * 131072 + n0, 256, 0, 512};
            c.sub[1] = {phi, plo, (const __half*)whh + (size_t)l * 131072 + n0, 256, 0, 512};
            c.nsub = 2; c.C = (float*)zrp + n0; c.ldc = 512;
            c.b0 = b_i2h + (size_t)l * 512 + n0; c.b1 = b_h2h + (size_t)l * 512 + n0;
        }
        // slots 4-7: g_acc halves (g01 -> gacc, g23 -> gacc2), nsub=2, nit=16
        for (int s = 4; s < 8; ++s) {
            Slot& c = P.s[s];
            int t = s - 4;
            int gh = t >> 1;              // 0: g=0,1 ; 1: g=2,3
            int n0 = (t & 1) * 128;
            for (int u = 0; u < 2; ++u) {
                int g = gh * 2 + u;
                c.sub[u] = {(const __half*)ash, (const __half*)asl,
                            (const __half*)wuh + ((size_t)l * 4 + g) * 65536 + n0,
                            1024, g * 256, 256};
            }
            c.nsub = 2; c.C = (float*)(gh ? gaccp2 : gaccp) + n0; c.ldc = 256;
            c.b0 = nullptr; c.b1 = nullptr;
        }
        // slots 8-9: cand (x@Wj^T + bias), N=256, nit=8 (shortest last)
        for (int s = 8; s < 10; ++s) {
            Slot& c = P.s[s];
            int n0 = 128 * (s - 8);
            c.sub[0] = {xhi, xlo, (const __half*)wjh + (size_t)l * 65536 + n0, 256, 0, 256};
            c.nsub = 1; c.C = (float*)candp + n0; c.ldc = 256;
            c.b0 = b_j1j + (size_t)l * 256 + n0; c.b1 = nullptr;
        }
        gemm_k<<<dim3(NBAT / 128, 10), 256, SMEMB>>>(P);

        pointwise_k<<<NBAT * 128 / 256, 256>>>(prev + (size_t)l * NBAT * NR,
                                               b_uij + (size_t)l * 1024,
                                               out + (size_t)l * NBAT * NR);
    }
}

// round 12
// speedup vs baseline: 2.9420x; 1.0271x over previous
#include <cuda_runtime.h>
#include <cuda_fp16.h>
#include <math.h>
#include <stdint.h>

#define NLAY 4
#define NBAT 16384
#define NR   256

// ======================= device scratch (no runtime alloc) =======================
__device__ __align__(16) __half d_xh[(size_t)NBAT * 256], d_xl[(size_t)NBAT * 256];
__device__ __align__(16) __half d_ph[(size_t)NLAY * NBAT * 256], d_pl[(size_t)NLAY * NBAT * 256];
__device__ __align__(16) __half d_ash[(size_t)NBAT * 1024], d_asl[(size_t)NBAT * 1024];
__device__ __align__(16) __half d_wih[(size_t)NLAY * 256 * 512];
__device__ __align__(16) __half d_whh[(size_t)NLAY * 256 * 512];
__device__ __align__(16) __half d_wjh[(size_t)NLAY * 256 * 256];
__device__ __align__(16) __half d_wuh[(size_t)NLAY * 4 * 256 * 256];
__device__ float g_ugacc[NBAT * 16];
__device__ float g_gvals[NBAT * 4];
__device__ float g_zr[(size_t)NBAT * 2 * NR];
__device__ float g_cand[(size_t)NBAT * NR];
__device__ float g_gacc[(size_t)NBAT * NR];     // partial: g=0,1
__device__ float g_gacc2[(size_t)NBAT * NR];    // partial: g=2,3

// ======================= PTX helpers (base sm_100 features only) =======================
__device__ __forceinline__ uint32_t s2u(const void* p) {
    uint32_t a;
    asm("{ .reg .u64 t; cvta.to.shared.u64 t, %1; cvt.u32.u64 %0, t; }" : "=r"(a) : "l"(p));
    return a;
}
__device__ __forceinline__ void cp16(uint32_t dst, const void* src) {
    asm volatile("cp.async.cg.shared.global [%0], [%1], 16;" ::"r"(dst), "l"(src) : "memory");
}
__device__ __forceinline__ void cp_commit() { asm volatile("cp.async.commit_group;" ::: "memory"); }
template <int N>
__device__ __forceinline__ void cp_wait() { asm volatile("cp.async.wait_group %0;" ::"n"(N) : "memory"); }
__device__ __forceinline__ void ldsm4(uint32_t* r, uint32_t a) {
    asm volatile("ldmatrix.sync.aligned.m8n8.x4.shared.b16 {%0,%1,%2,%3}, [%4];"
                 : "=r"(r[0]), "=r"(r[1]), "=r"(r[2]), "=r"(r[3]) : "r"(a));
}
__device__ __forceinline__ void ldsm4t(uint32_t* r, uint32_t a) {
    asm volatile("ldmatrix.sync.aligned.m8n8.x4.trans.shared.b16 {%0,%1,%2,%3}, [%4];"
                 : "=r"(r[0]), "=r"(r[1]), "=r"(r[2]), "=r"(r[3]) : "r"(a));
}
__device__ __forceinline__ void mma16816(float* c, const uint32_t* a, const uint32_t* b) {
    asm volatile(
        "mma.sync.aligned.m16n8k16.row.col.f32.f16.f16.f32 "
        "{%0,%1,%2,%3}, {%4,%5,%6,%7}, {%8,%9}, {%0,%1,%2,%3};"
        : "+f"(c[0]), "+f"(c[1]), "+f"(c[2]), "+f"(c[3])
        : "r"(a[0]), "r"(a[1]), "r"(a[2]), "r"(a[3]), "r"(b[0]), "r"(b[1]));
}
__device__ __forceinline__ void hsplit(float v, __half& h, __half& l) {
    h = __float2half_rn(v);
    l = __float2half_rn(v - __half2float(h));
}

// ======================= prep kernels =======================
__global__ void split_k(const float* __restrict__ src, __half* __restrict__ hi,
                        __half* __restrict__ lo) {
    size_t i = (size_t)blockIdx.x * 256 + threadIdx.x;
    float4 v = ((const float4*)src)[i];
    __half h0, h1, h2, h3, l0, l1, l2, l3;
    hsplit(v.x, h0, l0); hsplit(v.y, h1, l1); hsplit(v.z, h2, l2); hsplit(v.w, h3, l3);
    ((__half2*)hi)[2 * i]     = __halves2half2(h0, h1);
    ((__half2*)hi)[2 * i + 1] = __halves2half2(h2, h3);
    ((__half2*)lo)[2 * i]     = __halves2half2(l0, l1);
    ((__half2*)lo)[2 * i + 1] = __halves2half2(l2, l3);
}
__global__ void prep_w_k(const float* __restrict__ src, __half* __restrict__ hi, int rows) {
    __shared__ float t[32][33];
    const float* s = src + (size_t)blockIdx.z * rows * 256;
    __half* ho = hi + (size_t)blockIdx.z * rows * 256;
    int r0 = blockIdx.x * 32, c0 = blockIdx.y * 32;
#pragma unroll
    for (int i = threadIdx.y; i < 32; i += 8)
        t[i][threadIdx.x] = s[(size_t)(r0 + i) * 256 + c0 + threadIdx.x];
    __syncthreads();
#pragma unroll
    for (int i = threadIdx.y; i < 32; i += 8) {
        size_t o = (size_t)(c0 + i) * rows + r0 + threadIdx.x;
        ho[o] = __float2half_rn(t[threadIdx.x][i]);
    }
}
__global__ void gacc_prep_k(const float* __restrict__ prev) {
    uint32_t i = blockIdx.x * 256 + threadIdx.x;
    uint32_t e = i * 4, b = e >> 10, gk = e & 1023, g = gk >> 8, k = gk & 255;
    float s = g_gvals[b * 4 + g];
    float4 v = *(const float4*)(prev + ((size_t)g * NBAT + b) * 256 + k);
    v.x *= s; v.y *= s; v.z *= s; v.w *= s;
    __half h0, h1, h2, h3, l0, l1, l2, l3;
    hsplit(v.x, h0, l0); hsplit(v.y, h1, l1); hsplit(v.z, h2, l2); hsplit(v.w, h3, l3);
    size_t o = ((size_t)b * 1024 + gk) >> 1;
    ((__half2*)d_ash)[o]     = __halves2half2(h0, h1);
    ((__half2*)d_ash)[o + 1] = __halves2half2(h2, h3);
    ((__half2*)d_asl)[o]     = __halves2half2(l0, l1);
    ((__half2*)d_asl)[o + 1] = __halves2half2(l2, l3);
}

// ======================= warp-MMA 2-pass split GEMM =======================
struct Sub {
    const __half *Ahi, *Alo, *Bhi;   // B pre-offset to n0
    int aLen, aK0, bLen;
};
struct Slot {
    Sub sub[4];
    int nsub;
    float* C;            // pre-offset to n0
    int ldc;
    const float* b0;     // pre-offset to n0 (or null)
    const float* b1;
};
struct Params { Slot s[10]; };

#define STAGES 3
#define A_PITCH 80
#define B_PITCH 272
#define A_HALF (128 * A_PITCH)              // 10240
#define B_HALF (32 * B_PITCH)               // 8704
#define STAGEB (2 * A_HALF + B_HALF)        // 29184
#define SMEMB (STAGES * STAGEB)             // 87552

__global__ void __launch_bounds__(256, 2) gemm_k(const __grid_constant__ Params P) {
    extern __shared__ char sm[];
    const Slot& S = P.s[blockIdx.y];
    const int tid = threadIdx.x;
    const int bm = blockIdx.x * 128;
    const uint32_t sbase = s2u(sm);
    const int nit = S.nsub * 8;

    // warp grid 4x2: wm in [0,4) -> 32-row band, wn in [0,2) -> 64-col band.
    // A read 2x redundantly (was 4x), B 4x (was 2x): 16K*2 + 8K*4 = 64KB/iter vs 80KB.
    float acc[2][8][4];
#pragma unroll
    for (int a = 0; a < 2; ++a)
#pragma unroll
        for (int b = 0; b < 8; ++b)
#pragma unroll
            for (int c = 0; c < 4; ++c) acc[a][b][c] = 0.f;

    auto issue = [&](int it) {
        const int st = it % STAGES;
        const int sub = it >> 3, kc = it & 7;
        const Sub& sg = S.sub[sub];
        const uint32_t sa = sbase + st * STAGEB;
#pragma unroll
        for (int c = 0; c < 4; ++c) {
            int idx = tid + (c & 1) * 256;
            int r = idx >> 2, g = idx & 3;
            const __half* Ag = (c < 2) ? sg.Ahi : sg.Alo;
            uint32_t dst = sa + ((c < 2) ? 0 : A_HALF) + r * A_PITCH + g * 16;
            cp16(dst, Ag + (size_t)(bm + r) * sg.aLen + sg.aK0 + kc * 32 + g * 8);
        }
#pragma unroll
        for (int c = 0; c < 2; ++c) {
            int idx = tid + c * 256;
            int k = idx >> 4, gg = idx & 15;
            uint32_t dst = sa + 2 * A_HALF + k * B_PITCH + gg * 16;
            cp16(dst, sg.Bhi + (size_t)(kc * 32 + k) * sg.bLen + gg * 8);
        }
        cp_commit();
    };

    issue(0);
    issue(1);

    const int wid = tid >> 5, lane = tid & 31;
    const int wm = wid >> 1, wn = wid & 1;

    for (int it = 0; it < nit; ++it) {
        cp_wait<STAGES - 2>();
        __syncthreads();
        const uint32_t sa = sbase + (it % STAGES) * STAGEB;
        const uint32_t bBase = sa + 2 * A_HALF;
#pragma unroll
        for (int kh = 0; kh < 2; ++kh) {
            uint32_t afh[2][4], afl[2][4];
#pragma unroll
            for (int mi = 0; mi < 2; ++mi) {
                int row = wm * 32 + mi * 16 + (lane & 15);
                int cofs = (kh * 2 + (lane >> 4)) * 16;
                ldsm4(afh[mi], sa + row * A_PITCH + cofs);
                ldsm4(afl[mi], sa + A_HALF + row * A_PITCH + cofs);
            }
            uint32_t bf[8][2];
#pragma unroll
            for (int j = 0; j < 4; ++j) {
                int g4 = lane >> 3;
                int krow = kh * 16 + (g4 & 1) * 8 + (lane & 7);
                int gcol = (wn * 64 + j * 16 + (g4 >> 1) * 8) >> 3;
                uint32_t r[4];
                ldsm4t(r, bBase + krow * B_PITCH + gcol * 16);
                bf[2 * j][0] = r[0]; bf[2 * j][1] = r[1];
                bf[2 * j + 1][0] = r[2]; bf[2 * j + 1][1] = r[3];
            }
#pragma unroll
            for (int mi = 0; mi < 2; ++mi)
#pragma unroll
                for (int ni = 0; ni < 8; ++ni) mma16816(acc[mi][ni], afh[mi], bf[ni]);
#pragma unroll
            for (int mi = 0; mi < 2; ++mi)
#pragma unroll
                for (int ni = 0; ni < 8; ++ni) mma16816(acc[mi][ni], afl[mi], bf[ni]);
        }
        __syncthreads();
        if (it + STAGES - 1 < nit) issue(it + STAGES - 1);
    }

    // epilogue: direct fp32 stores + bias
#pragma unroll
    for (int mi = 0; mi < 2; ++mi) {
        int r0 = bm + wm * 32 + mi * 16 + (lane >> 2);
#pragma unroll
        for (int ni = 0; ni < 8; ++ni) {
            int col = wn * 64 + ni * 8 + (lane & 3) * 2;
            float bv0 = 0.f, bv1 = 0.f;
            if (S.b0) { bv0 = S.b0[col]; bv1 = S.b0[col + 1]; }
            if (S.b1) { bv0 += S.b1[col]; bv1 += S.b1[col + 1]; }
            float2 v0 = {acc[mi][ni][0] + bv0, acc[mi][ni][1] + bv1};
            float2 v1 = {acc[mi][ni][2] + bv0, acc[mi][ni][3] + bv1};
            *(float2*)(S.C + (size_t)r0 * S.ldc + col) = v0;
            *(float2*)(S.C + (size_t)(r0 + 8) * S.ldc + col) = v1;
        }
    }
}

// ======================= small fp32 kernels =======================
__global__ void ug_precompute_k(const float* __restrict__ prev, const float* __restrict__ wug) {
    __shared__ float ws[8 * 1024];
    const int ljbase = blockIdx.y * 8;
    {
        const float4* src = (const float4*)(wug + (size_t)ljbase * 1024);
        float4* dst = (float4*)ws;
#pragma unroll
        for (int i = 0; i < 8; ++i) dst[threadIdx.x + i * 256] = src[threadIdx.x + i * 256];
    }
    __syncthreads();
    const int warp = threadIdx.x >> 5, lane = threadIdx.x & 31;
    const int b = blockIdx.x * 8 + warp;
    float acc[8];
#pragma unroll
    for (int t = 0; t < 8; ++t) acc[t] = 0.f;
#pragma unroll
    for (int g = 0; g < 4; ++g) {
        const float* hrow = prev + ((size_t)g * NBAT + b) * 256;
#pragma unroll
        for (int rr = 0; rr < 8; ++rr) {
            int r = rr * 32 + lane;
            float h = hrow[r];
#pragma unroll
            for (int t = 0; t < 8; ++t) acc[t] += h * ws[t * 1024 + g * 256 + r];
        }
    }
#pragma unroll
    for (int t = 0; t < 8; ++t) {
        float v = acc[t];
#pragma unroll
        for (int o = 16; o > 0; o >>= 1) v += __shfl_xor_sync(0xffffffffu, v, o);
        if (lane == 0) g_ugacc[(size_t)b * 16 + ljbase + t] = v;
    }
}

__global__ void xg_k(const float* __restrict__ xl, const float* __restrict__ wg,
                     const float* __restrict__ bg, const float* __restrict__ bug, int l) {
    __shared__ float ws[1024];
#pragma unroll
    for (int i = 0; i < 4; ++i) ws[threadIdx.x + i * 256] = wg[threadIdx.x + i * 256];
    __syncthreads();
    const int warp = threadIdx.x >> 5, lane = threadIdx.x & 31;
    const int b = blockIdx.x * 8 + warp;
    const float* xrow = xl + (size_t)b * 256;
    float acc[4] = {0.f, 0.f, 0.f, 0.f};
#pragma unroll
    for (int rr = 0; rr < 8; ++rr) {
        int r = rr * 32 + lane;
        float xv = xrow[r];
#pragma unroll
        for (int j = 0; j < 4; ++j) acc[j] += xv * ws[j * 256 + r];
    }
#pragma unroll
    for (int j = 0; j < 4; ++j) {
        float v = acc[j];
#pragma unroll
        for (int o = 16; o > 0; o >>= 1) v += __shfl_xor_sync(0xffffffffu, v, o);
        if (lane == 0)
            g_gvals[b * 4 + j] = tanhf(v + g_ugacc[(size_t)b * 16 + l * 4 + j] + bg[j] + bug[j]);
    }
}

// GRU pointwise: gacc = partialA + partialB (+ g-weighted b_uij); split h_t for next layer
__global__ void pointwise_k(const float* __restrict__ hprev, const float* __restrict__ buij,
                            float* __restrict__ out) {
    __shared__ float sbu[1024];
#pragma unroll
    for (int i = 0; i < 4; ++i) sbu[threadIdx.x + i * 256] = buij[threadIdx.x + i * 256];
    __syncthreads();
    uint32_t i = blockIdx.x * 256 + threadIdx.x;
    uint32_t b = i >> 7, j = (i & 127) * 2;
    float g0 = g_gvals[b * 4 + 0], g1 = g_gvals[b * 4 + 1];
    float g2 = g_gvals[b * 4 + 2], g3 = g_gvals[b * 4 + 3];
    __half hh[2], hl[2];
#pragma unroll
    for (int u = 0; u < 2; ++u) {
        uint32_t r = j + u;
        float zpre = g_zr[(size_t)b * 512 + r];
        float rpre = g_zr[(size_t)b * 512 + 256 + r];
        float z = 1.f / (1.f + expf(-zpre));
        float rt = 1.f / (1.f + expf(-rpre));
        size_t br = (size_t)b * 256 + r;
        float gt = g_gacc[br] + g_gacc2[br] + g0 * sbu[r] + g1 * sbu[256 + r] +
                   g2 * sbu[512 + r] + g3 * sbu[768 + r];
        float hc = tanhf(g_cand[br] + rt * gt);
        float h = (1.f - z) * hprev[br] + z * hc;
        out[br] = h;
        hsplit(h, hh[u], hl[u]);
    }
    size_t o = ((size_t)b * 256 + j) >> 1;
    ((__half2*)d_xh)[o] = __halves2half2(hh[0], hh[1]);
    ((__half2*)d_xl)[o] = __halves2half2(hl[0], hl[1]);
}

// ======================= launch =======================
extern "C" void kernel_launch(void* const* d_in, const int* in_sizes, int n_in,
                              void* d_out, int out_size) {
    (void)in_sizes; (void)n_in; (void)out_size;
    const float* x     = (const float*)d_in[0];
    const float* prev  = (const float*)d_in[1];
    const float* w_i2h = (const float*)d_in[2];
    const float* b_i2h = (const float*)d_in[3];
    const float* w_h2h = (const float*)d_in[4];
    const float* b_h2h = (const float*)d_in[5];
    const float* w_j1j = (const float*)d_in[6];
    const float* b_j1j = (const float*)d_in[7];
    const float* w_g   = (const float*)d_in[8];
    const float* b_g   = (const float*)d_in[9];
    const float* w_ug  = (const float*)d_in[10];
    const float* b_ug  = (const float*)d_in[11];
    const float* w_uij = (const float*)d_in[12];
    const float* b_uij = (const float*)d_in[13];
    float* out = (float*)d_out;

    void *xh, *xl, *ph, *pl, *ash, *asl;
    void *wih, *whh, *wjh, *wuh;
    void *zrp, *candp, *gaccp, *gaccp2;
    cudaGetSymbolAddress(&xh, d_xh);   cudaGetSymbolAddress(&xl, d_xl);
    cudaGetSymbolAddress(&ph, d_ph);   cudaGetSymbolAddress(&pl, d_pl);
    cudaGetSymbolAddress(&ash, d_ash); cudaGetSymbolAddress(&asl, d_asl);
    cudaGetSymbolAddress(&wih, d_wih); cudaGetSymbolAddress(&whh, d_whh);
    cudaGetSymbolAddress(&wjh, d_wjh); cudaGetSymbolAddress(&wuh, d_wuh);
    cudaGetSymbolAddress(&zrp, g_zr);  cudaGetSymbolAddress(&candp, g_cand);
    cudaGetSymbolAddress(&gaccp, g_gacc); cudaGetSymbolAddress(&gaccp2, g_gacc2);
    cudaFuncSetAttribute(gemm_k, cudaFuncAttributeMaxDynamicSharedMemorySize, SMEMB);

    // ---- upfront operand prep ----
    split_k<<<NBAT * 256 / 1024, 256>>>(x, (__half*)xh, (__half*)xl);
    split_k<<<NLAY * NBAT * 256 / 1024, 256>>>(prev, (__half*)ph, (__half*)pl);
    prep_w_k<<<dim3(16, 8, 4), dim3(32, 8)>>>(w_i2h, (__half*)wih, 512);
    prep_w_k<<<dim3(16, 8, 4), dim3(32, 8)>>>(w_h2h, (__half*)whh, 512);
    prep_w_k<<<dim3(8, 8, 4), dim3(32, 8)>>>(w_j1j, (__half*)wjh, 256);
    prep_w_k<<<dim3(8, 8, 16), dim3(32, 8)>>>(w_uij, (__half*)wuh, 256);
    ug_precompute_k<<<dim3(NBAT / 8, 2), 256>>>(prev, w_ug);

    for (int l = 0; l < NLAY; ++l) {
        const float* xlf = (l == 0) ? x : out + (size_t)(l - 1) * NBAT * NR;
        xg_k<<<NBAT / 8, 256>>>(xlf, w_g + (size_t)l * 1024, b_g + l * 4, b_ug + l * 4, l);
        gacc_prep_k<<<NBAT * 1024 / 1024, 256>>>(prev);

        Params P;
        const __half* xhi = (const __half*)xh;
        const __half* xlo = (const __half*)xl;
        const __half* phi = (const __half*)ph + (size_t)l * NBAT * 256;
        const __half* plo = (const __half*)pl + (size_t)l * NBAT * 256;
        // slots 0-3: zr (x@Wi^T + h_l@Wh^T), n0 = 128*s, N=512, nit=16
        for (int s = 0; s < 4; ++s) {
            Slot& c = P.s[s];
            int n0 = 128 * s;
            c.sub[0] = {xhi, xlo, (const __half*)wih + (size_t)l * 131072 + n0, 256, 0, 512};
            c.sub[1] = {phi, plo, (const __half*)whh + (size_t)l * 131072 + n0, 256, 0, 512};
            c.nsub = 2; c.C = (float*)zrp + n0; c.ldc = 512;
            c.b0 = b_i2h + (size_t)l * 512 + n0; c.b1 = b_h2h + (size_t)l * 512 + n0;
        }
        // slots 4-7: g_acc halves (g01 -> gacc, g23 -> gacc2), nsub=2, nit=16
        for (int s = 4; s < 8; ++s) {
            Slot& c = P.s[s];
            int t = s - 4;
            int gh = t >> 1;
            int n0 = (t & 1) * 128;
            for (int u = 0; u < 2; ++u) {
                int g = gh * 2 + u;
                c.sub[u] = {(const __half*)ash, (const __half*)asl,
                            (const __half*)wuh + ((size_t)l * 4 + g) * 65536 + n0,
                            1024, g * 256, 256};
            }
            c.nsub = 2; c.C = (float*)(gh ? gaccp2 : gaccp) + n0; c.ldc = 256;
            c.b0 = nullptr; c.b1 = nullptr;
        }
        // slots 8-9: cand (x@Wj^T + bias), N=256, nit=8 (shortest last)
        for (int s = 8; s < 10; ++s) {
            Slot& c = P.s[s];
            int n0 = 128 * (s - 8);
            c.sub[0] = {xhi, xlo, (const __half*)wjh + (size_t)l * 65536 + n0, 256, 0, 256};
            c.nsub = 1; c.C = (float*)candp + n0; c.ldc = 256;
            c.b0 = b_j1j + (size_t)l * 256 + n0; c.b1 = nullptr;
        }
        gemm_k<<<dim3(NBAT / 128, 10), 256, SMEMB>>>(P);

        pointwise_k<<<NBAT * 128 / 256, 256>>>(prev + (size_t)l * NBAT * NR,
                                               b_uij + (size_t)l * 1024,
                                               out + (size_t)l * NBAT * NR);
    }
}